// round 1
// baseline (speedup 1.0000x reference)
#include <cuda_runtime.h>
#include <math.h>

#define LSEQ 4096
#define DMODEL 1024
#define NHEAD 16
#define DHEAD 64

// ---------------- scratch (no allocations allowed) ----------------
__device__ float g_Q[LSEQ * DMODEL];
__device__ float g_K[LSEQ * DMODEL];
__device__ float g_V[LSEQ * DMODEL];
__device__ float g_A[LSEQ * DMODEL];
__device__ float g_cos[LSEQ * 32];
__device__ float g_sin[LSEQ * 32];

// ---------------- GEMM: C[M,N] = A[M,K] * B[N,K]^T --------------
// M=4096, N=1024, K=1024. Block tile 64x64, BK=16, 256 threads, 4x4 micro.
__global__ __launch_bounds__(256) void gemm_nt_kernel(
    const float* __restrict__ A, const float* __restrict__ B,
    float* __restrict__ C) {
    __shared__ float As[16][68];
    __shared__ float Bs[16][68];

    const int tid = threadIdx.x;
    const int tx = tid & 15;        // 0..15 -> N micro
    const int ty = tid >> 4;        // 0..15 -> M micro
    const int bm = blockIdx.x * 64;
    const int bn = blockIdx.y * 64;

    const int lrow = tid >> 2;          // 0..63
    const int lk4  = (tid & 3) << 2;    // 0,4,8,12

    const float* Ap = A + (size_t)(bm + lrow) * DMODEL + lk4;
    const float* Bp = B + (size_t)(bn + lrow) * DMODEL + lk4;

    float acc[4][4];
#pragma unroll
    for (int i = 0; i < 4; i++)
#pragma unroll
        for (int j = 0; j < 4; j++) acc[i][j] = 0.f;

    for (int k0 = 0; k0 < DMODEL; k0 += 16) {
        float4 av = *reinterpret_cast<const float4*>(Ap + k0);
        float4 bv = *reinterpret_cast<const float4*>(Bp + k0);
        As[lk4 + 0][lrow] = av.x; As[lk4 + 1][lrow] = av.y;
        As[lk4 + 2][lrow] = av.z; As[lk4 + 3][lrow] = av.w;
        Bs[lk4 + 0][lrow] = bv.x; Bs[lk4 + 1][lrow] = bv.y;
        Bs[lk4 + 2][lrow] = bv.z; Bs[lk4 + 3][lrow] = bv.w;
        __syncthreads();

#pragma unroll
        for (int kk = 0; kk < 16; kk++) {
            const float4 a = *reinterpret_cast<const float4*>(&As[kk][ty << 2]);
            const float4 b = *reinterpret_cast<const float4*>(&Bs[kk][tx << 2]);
            float ar[4] = {a.x, a.y, a.z, a.w};
            float br[4] = {b.x, b.y, b.z, b.w};
#pragma unroll
            for (int i = 0; i < 4; i++)
#pragma unroll
                for (int j = 0; j < 4; j++) acc[i][j] += ar[i] * br[j];
        }
        __syncthreads();
    }

#pragma unroll
    for (int i = 0; i < 4; i++) {
        float4 v = make_float4(acc[i][0], acc[i][1], acc[i][2], acc[i][3]);
        *reinterpret_cast<float4*>(C + (size_t)(bm + (ty << 2) + i) * DMODEL + bn + (tx << 2)) = v;
    }
}

// ---------------- RoPE tables --------------------------------
__global__ void rope_tables_kernel() {
    int l = blockIdx.x;
    int j = threadIdx.x;   // 0..31
    float e = (float)(2 * j) / 64.0f;
    float inv = (float)pow(10000.0, -(double)e);
    float freq = (float)l * inv;               // fp32 product, matches reference
    double s, c;
    sincos((double)freq, &s, &c);
    g_cos[l * 32 + j] = (float)c;
    g_sin[l * 32 + j] = (float)s;
}

// ---------------- RoPE apply (in place, warp per (l,h)) -------
__global__ __launch_bounds__(128) void rope_apply_kernel(float* __restrict__ Q,
                                                         float* __restrict__ K) {
    int gw = blockIdx.x * 4 + (threadIdx.x >> 5);
    int lane = threadIdx.x & 31;
    int l = gw >> 4;
    int h = gw & 15;
    float c = g_cos[l * 32 + lane];
    float s = g_sin[l * 32 + lane];
    float* q = Q + (size_t)l * DMODEL + h * DHEAD;
    float* k = K + (size_t)l * DMODEL + h * DHEAD;
    float q1 = q[2 * lane], q2 = q[2 * lane + 1];
    float k1 = k[2 * lane], k2 = k[2 * lane + 1];
    __syncwarp();
    q[lane]      = q1 * c - q2 * s;
    q[lane + 32] = q1 * s + q2 * c;
    k[lane]      = k1 * c - k2 * s;
    k[lane + 32] = k1 * s + k2 * c;
}

// ---------------- causal flash attention (fp32) ---------------
// grid: (L/128, H). 128 threads; thread t owns query row blk*128+t.
__global__ __launch_bounds__(128) void flash_kernel(
    const float* __restrict__ Q, const float* __restrict__ K,
    const float* __restrict__ V, float* __restrict__ O) {
    __shared__ float4 Ks[32][16];
    __shared__ float4 Vs[32][16];

    const int h = blockIdx.y;
    const int qrow = blockIdx.x * 128 + threadIdx.x;
    const float NEG_INF = __int_as_float(0xff800000);

    float q[64];
    {
        const float* qp = Q + (size_t)qrow * DMODEL + h * DHEAD;
#pragma unroll
        for (int i = 0; i < 16; i++) {
            float4 v = *reinterpret_cast<const float4*>(qp + 4 * i);
            q[4 * i + 0] = v.x; q[4 * i + 1] = v.y;
            q[4 * i + 2] = v.z; q[4 * i + 3] = v.w;
        }
    }
    float o[64];
#pragma unroll
    for (int i = 0; i < 64; i++) o[i] = 0.f;
    float m = NEG_INF;
    float lsum = 0.f;

    const int kmax = (blockIdx.x + 1) * 128;   // block-level causal bound
    for (int k0 = 0; k0 < kmax; k0 += 32) {
        __syncthreads();
#pragma unroll
        for (int t = 0; t < 4; t++) {
            int idx = threadIdx.x + t * 128;
            int row = idx >> 4, col = idx & 15;
            const float* kp = K + (size_t)(k0 + row) * DMODEL + (h << 6) + (col << 2);
            const float* vp = V + (size_t)(k0 + row) * DMODEL + (h << 6) + (col << 2);
            Ks[row][col] = *reinterpret_cast<const float4*>(kp);
            Vs[row][col] = *reinterpret_cast<const float4*>(vp);
        }
        __syncthreads();

        for (int c = 0; c < 32; c += 16) {
            float s[16];
#pragma unroll
            for (int j = 0; j < 16; j++) {
                float acc = 0.f;
#pragma unroll
                for (int d4 = 0; d4 < 16; d4++) {
                    float4 kv = Ks[c + j][d4];
                    acc += q[4 * d4 + 0] * kv.x;
                    acc += q[4 * d4 + 1] * kv.y;
                    acc += q[4 * d4 + 2] * kv.z;
                    acc += q[4 * d4 + 3] * kv.w;
                }
                int kidx = k0 + c + j;
                s[j] = (kidx <= qrow) ? acc * 0.125f : NEG_INF;
            }
            float mnew = m;
#pragma unroll
            for (int j = 0; j < 16; j++) mnew = fmaxf(mnew, s[j]);
            float alpha = __expf(m - mnew);
            m = mnew;
            lsum *= alpha;
#pragma unroll
            for (int d = 0; d < 64; d++) o[d] *= alpha;
#pragma unroll
            for (int j = 0; j < 16; j++) {
                float p = __expf(s[j] - m);
                lsum += p;
#pragma unroll
                for (int d4 = 0; d4 < 16; d4++) {
                    float4 vv = Vs[c + j][d4];
                    o[4 * d4 + 0] += p * vv.x;
                    o[4 * d4 + 1] += p * vv.y;
                    o[4 * d4 + 2] += p * vv.z;
                    o[4 * d4 + 3] += p * vv.w;
                }
            }
        }
    }

    float rl = 1.f / lsum;
    float* op = O + (size_t)qrow * DMODEL + h * DHEAD;
#pragma unroll
    for (int i = 0; i < 16; i++) {
        float4 v = make_float4(o[4 * i + 0] * rl, o[4 * i + 1] * rl,
                               o[4 * i + 2] * rl, o[4 * i + 3] * rl);
        *reinterpret_cast<float4*>(op + 4 * i) = v;
    }
}

// ---------------- launch ---------------------------------------
extern "C" void kernel_launch(void* const* d_in, const int* in_sizes, int n_in,
                              void* d_out, int out_size) {
    const float* x  = (const float*)d_in[0];
    // d_in[1] = mask (tril) — fixed causal, hardcoded in flash kernel
    const float* Wq = (const float*)d_in[2];
    const float* Wk = (const float*)d_in[3];
    const float* Wv = (const float*)d_in[4];
    const float* Wo = (const float*)d_in[5];
    float* out = (float*)d_out;

    float *Qp, *Kp, *Vp, *Ap;
    cudaGetSymbolAddress((void**)&Qp, g_Q);
    cudaGetSymbolAddress((void**)&Kp, g_K);
    cudaGetSymbolAddress((void**)&Vp, g_V);
    cudaGetSymbolAddress((void**)&Ap, g_A);

    rope_tables_kernel<<<LSEQ, 32>>>();

    dim3 ggrid(LSEQ / 64, DMODEL / 64);
    gemm_nt_kernel<<<ggrid, 256>>>(x, Wq, Qp);
    gemm_nt_kernel<<<ggrid, 256>>>(x, Wk, Kp);
    gemm_nt_kernel<<<ggrid, 256>>>(x, Wv, Vp);

    rope_apply_kernel<<<(LSEQ * NHEAD) / 4, 128>>>(Qp, Kp);

    dim3 fgrid(LSEQ / 128, NHEAD);
    flash_kernel<<<fgrid, 128>>>(Qp, Kp, Vp, Ap);

    gemm_nt_kernel<<<ggrid, 256>>>(Ap, Wo, out);
}

// round 4
// speedup vs baseline: 1.2714x; 1.2714x over previous
#include <cuda_runtime.h>
#include <cuda_bf16.h>
#include <math.h>
#include <stdint.h>

#define LSEQ 4096
#define DMODEL 1024
#define NHEAD 16
#define DHEAD 64

// ---------------- scratch (no allocations allowed) ----------------
__device__ float g_Q[LSEQ * DMODEL];
__device__ float g_K[LSEQ * DMODEL];
__device__ float g_V[LSEQ * DMODEL];
__device__ float g_A[LSEQ * DMODEL];
__device__ float g_cos[LSEQ * 32];
__device__ float g_sin[LSEQ * 32];

// =================== helpers ===================
__device__ __forceinline__ uint32_t smem_u32(const void* p) {
    uint32_t a;
    asm("{ .reg .u64 t; cvta.to.shared.u64 t, %1; cvt.u32.u64 %0, t; }"
        : "=r"(a) : "l"(p));
    return a;
}

__device__ __forceinline__ void ldsm_x4(uint32_t& r0, uint32_t& r1,
                                        uint32_t& r2, uint32_t& r3,
                                        uint32_t addr) {
    asm volatile("ldmatrix.sync.aligned.m8n8.x4.shared.b16 {%0,%1,%2,%3}, [%4];"
                 : "=r"(r0), "=r"(r1), "=r"(r2), "=r"(r3) : "r"(addr));
}

__device__ __forceinline__ void mma16816(float* d, const uint32_t* a,
                                         const uint32_t* b) {
    asm volatile(
        "mma.sync.aligned.m16n8k16.row.col.f32.bf16.bf16.f32 "
        "{%0,%1,%2,%3}, {%4,%5,%6,%7}, {%8,%9}, {%0,%1,%2,%3};"
        : "+f"(d[0]), "+f"(d[1]), "+f"(d[2]), "+f"(d[3])
        : "r"(a[0]), "r"(a[1]), "r"(a[2]), "r"(a[3]), "r"(b[0]), "r"(b[1]));
}

// ======== bf16x3 HMMA GEMM: C[4096,1024] = A[4096,1024] @ B[1024,1024]^T =====
// Block 128x128, BK=32, 256 threads (8 warps: 4 m x 2 n), warp tile 32x64.
#define BM 128
#define BN 128
#define BK 32
#define ROWB 80                       // 32 bf16 = 64B data + 16B pad
#define OFF_AH 0
#define OFF_AL (128 * ROWB)
#define OFF_BH (2 * 128 * ROWB)
#define OFF_BL (3 * 128 * ROWB)
#define STAGE_BYTES (4 * 128 * ROWB)  // 40960
#define GEMM_SMEM (2 * STAGE_BYTES)   // 81920

// writes hi at sm+off, lo at sm+off+10240 (the AL/BL region follows AH/BH)
__device__ __forceinline__ void cvt_sts(char* sm, uint32_t off, float4 v) {
    __nv_bfloat162 h01 = __float22bfloat162_rn(make_float2(v.x, v.y));
    __nv_bfloat162 h23 = __float22bfloat162_rn(make_float2(v.z, v.w));
    float2 hf01 = __bfloat1622float2(h01);
    float2 hf23 = __bfloat1622float2(h23);
    __nv_bfloat162 l01 = __float22bfloat162_rn(
        make_float2(v.x - hf01.x, v.y - hf01.y));
    __nv_bfloat162 l23 = __float22bfloat162_rn(
        make_float2(v.z - hf23.x, v.w - hf23.y));
    uint2 hq, lq;
    hq.x = *reinterpret_cast<uint32_t*>(&h01);
    hq.y = *reinterpret_cast<uint32_t*>(&h23);
    lq.x = *reinterpret_cast<uint32_t*>(&l01);
    lq.y = *reinterpret_cast<uint32_t*>(&l23);
    *reinterpret_cast<uint2*>(sm + off) = hq;
    *reinterpret_cast<uint2*>(sm + off + (uint32_t)(OFF_AL - OFF_AH)) = lq;
}

__global__ __launch_bounds__(256, 1) void gemm_mma_kernel(
    const float* __restrict__ A, const float* __restrict__ B,
    float* __restrict__ C) {
    extern __shared__ char smem[];
    const uint32_t sbase = smem_u32(smem);
    const int tid = threadIdx.x;
    const int wid = tid >> 5;
    const int lane = tid & 31;
    const int warp_m = wid & 3;    // 4 warps over M (32 rows each)
    const int warp_n = wid >> 2;   // 2 warps over N (64 cols each)
    const int bm = blockIdx.x * BM;
    const int bn = blockIdx.y * BN;

    float acc[2][8][4];
#pragma unroll
    for (int i = 0; i < 2; i++)
#pragma unroll
        for (int j = 0; j < 8; j++)
#pragma unroll
            for (int k = 0; k < 4; k++) acc[i][j][k] = 0.f;

    // loader coords: row = tid>>1, float4 slots (tid&1)*4 + j (j=0..3)
    const int lrow = tid >> 1;
    const int lslot = (tid & 1) * 4;          // base float4 slot (0 or 4)

    // ldmatrix lane addressing
    const int a_row = lane & 15;
    const int a_byte = (lane >> 4) << 4;
    const int b_grp = lane >> 3;
    const int b_row = (lane & 7) + ((b_grp >> 1) << 3);
    const int b_byte = (b_grp & 1) << 4;

    const float* Arow = A + (size_t)(bm + lrow) * DMODEL + lslot * 4;
    const float* Brow = B + (size_t)(bn + lrow) * DMODEL + lslot * 4;

    // ---- prologue: load chunk 0 to smem stage 0 ----
#pragma unroll
    for (int j = 0; j < 4; j++) {
        float4 av = *reinterpret_cast<const float4*>(Arow + j * 4);
        float4 bv = *reinterpret_cast<const float4*>(Brow + j * 4);
        uint32_t off = lrow * ROWB + (lslot + j) * 8;
        cvt_sts(smem + OFF_AH, off, av);
        cvt_sts(smem + OFF_BH, off, bv);
    }
    __syncthreads();

    float4 va[4], vb[4];
    for (int c = 0; c < 32; c++) {
        const int cur = c & 1;
        // prefetch next chunk into registers
        if (c < 31) {
            const int kb = (c + 1) * BK;
#pragma unroll
            for (int j = 0; j < 4; j++) {
                va[j] = *reinterpret_cast<const float4*>(Arow + kb + j * 4);
                vb[j] = *reinterpret_cast<const float4*>(Brow + kb + j * 4);
            }
        }

        // ---- compute on stage cur ----
        const uint32_t st = sbase + cur * STAGE_BYTES;
        const uint32_t sAh = st + OFF_AH + (warp_m * 32 + a_row) * ROWB + a_byte;
        const uint32_t sAl = st + OFF_AL + (warp_m * 32 + a_row) * ROWB + a_byte;
        const uint32_t sBh = st + OFF_BH + (warp_n * 64 + b_row) * ROWB + b_byte;
        const uint32_t sBl = st + OFF_BL + (warp_n * 64 + b_row) * ROWB + b_byte;
#pragma unroll
        for (int ks = 0; ks < 2; ks++) {
            uint32_t ah[2][4], al[2][4], bh[8][2], bl[8][2];
#pragma unroll
            for (int mt = 0; mt < 2; mt++) {
                ldsm_x4(ah[mt][0], ah[mt][1], ah[mt][2], ah[mt][3],
                        sAh + mt * 16 * ROWB + ks * 32);
                ldsm_x4(al[mt][0], al[mt][1], al[mt][2], al[mt][3],
                        sAl + mt * 16 * ROWB + ks * 32);
            }
#pragma unroll
            for (int np = 0; np < 4; np++) {
                ldsm_x4(bh[2 * np][0], bh[2 * np][1], bh[2 * np + 1][0],
                        bh[2 * np + 1][1], sBh + np * 16 * ROWB + ks * 32);
                ldsm_x4(bl[2 * np][0], bl[2 * np][1], bl[2 * np + 1][0],
                        bl[2 * np + 1][1], sBl + np * 16 * ROWB + ks * 32);
            }
#pragma unroll
            for (int mt = 0; mt < 2; mt++)
#pragma unroll
                for (int nt = 0; nt < 8; nt++) {
                    mma16816(acc[mt][nt], ah[mt], bh[nt]);
                    mma16816(acc[mt][nt], ah[mt], bl[nt]);
                    mma16816(acc[mt][nt], al[mt], bh[nt]);
                }
        }
        __syncthreads();

        // ---- store prefetched chunk to other stage ----
        if (c < 31) {
            char* sn = smem + (cur ^ 1) * STAGE_BYTES;
#pragma unroll
            for (int j = 0; j < 4; j++) {
                uint32_t off = lrow * ROWB + (lslot + j) * 8;
                cvt_sts(sn + OFF_AH, off, va[j]);
                cvt_sts(sn + OFF_BH, off, vb[j]);
            }
            __syncthreads();
        }
    }

    // ---- epilogue ----
#pragma unroll
    for (int mt = 0; mt < 2; mt++) {
        const int r0 = bm + warp_m * 32 + mt * 16 + (lane >> 2);
#pragma unroll
        for (int nt = 0; nt < 8; nt++) {
            const int col = bn + warp_n * 64 + nt * 8 + (lane & 3) * 2;
            *reinterpret_cast<float2*>(C + (size_t)r0 * DMODEL + col) =
                make_float2(acc[mt][nt][0], acc[mt][nt][1]);
            *reinterpret_cast<float2*>(C + (size_t)(r0 + 8) * DMODEL + col) =
                make_float2(acc[mt][nt][2], acc[mt][nt][3]);
        }
    }
}

// ---------------- RoPE tables --------------------------------
__global__ void rope_tables_kernel() {
    int l = blockIdx.x;
    int j = threadIdx.x;   // 0..31
    float e = (float)(2 * j) / 64.0f;
    float inv = (float)pow(10000.0, -(double)e);
    float freq = (float)l * inv;               // fp32 product, matches reference
    double s, c;
    sincos((double)freq, &s, &c);
    g_cos[l * 32 + j] = (float)c;
    g_sin[l * 32 + j] = (float)s;
}

// ---------------- RoPE apply (in place, warp per (l,h)) -------
__global__ __launch_bounds__(128) void rope_apply_kernel(float* __restrict__ Q,
                                                         float* __restrict__ K) {
    int gw = blockIdx.x * 4 + (threadIdx.x >> 5);
    int lane = threadIdx.x & 31;
    int l = gw >> 4;
    int h = gw & 15;
    float c = g_cos[l * 32 + lane];
    float s = g_sin[l * 32 + lane];
    float* q = Q + (size_t)l * DMODEL + h * DHEAD;
    float* k = K + (size_t)l * DMODEL + h * DHEAD;
    float q1 = q[2 * lane], q2 = q[2 * lane + 1];
    float k1 = k[2 * lane], k2 = k[2 * lane + 1];
    __syncwarp();
    q[lane]      = q1 * c - q2 * s;
    q[lane + 32] = q1 * s + q2 * c;
    k[lane]      = k1 * c - k2 * s;
    k[lane + 32] = k1 * s + k2 * c;
}

// ---------------- causal flash attention (fp32) ---------------
__global__ __launch_bounds__(128) void flash_kernel(
    const float* __restrict__ Q, const float* __restrict__ K,
    const float* __restrict__ V, float* __restrict__ O) {
    __shared__ float4 Ks[32][16];
    __shared__ float4 Vs[32][16];

    const int h = blockIdx.y;
    const int qrow = blockIdx.x * 128 + threadIdx.x;
    const float NEG_INF = __int_as_float(0xff800000);

    float q[64];
    {
        const float* qp = Q + (size_t)qrow * DMODEL + h * DHEAD;
#pragma unroll
        for (int i = 0; i < 16; i++) {
            float4 v = *reinterpret_cast<const float4*>(qp + 4 * i);
            q[4 * i + 0] = v.x; q[4 * i + 1] = v.y;
            q[4 * i + 2] = v.z; q[4 * i + 3] = v.w;
        }
    }
    float o[64];
#pragma unroll
    for (int i = 0; i < 64; i++) o[i] = 0.f;
    float m = NEG_INF;
    float lsum = 0.f;

    const int kmax = (blockIdx.x + 1) * 128;
    for (int k0 = 0; k0 < kmax; k0 += 32) {
        __syncthreads();
#pragma unroll
        for (int t = 0; t < 4; t++) {
            int idx = threadIdx.x + t * 128;
            int row = idx >> 4, col = idx & 15;
            const float* kp = K + (size_t)(k0 + row) * DMODEL + (h << 6) + (col << 2);
            const float* vp = V + (size_t)(k0 + row) * DMODEL + (h << 6) + (col << 2);
            Ks[row][col] = *reinterpret_cast<const float4*>(kp);
            Vs[row][col] = *reinterpret_cast<const float4*>(vp);
        }
        __syncthreads();

        for (int c = 0; c < 32; c += 16) {
            float s[16];
#pragma unroll
            for (int j = 0; j < 16; j++) {
                float acc2 = 0.f;
#pragma unroll
                for (int d4 = 0; d4 < 16; d4++) {
                    float4 kv = Ks[c + j][d4];
                    acc2 += q[4 * d4 + 0] * kv.x;
                    acc2 += q[4 * d4 + 1] * kv.y;
                    acc2 += q[4 * d4 + 2] * kv.z;
                    acc2 += q[4 * d4 + 3] * kv.w;
                }
                int kidx = k0 + c + j;
                s[j] = (kidx <= qrow) ? acc2 * 0.125f : NEG_INF;
            }
            float mnew = m;
#pragma unroll
            for (int j = 0; j < 16; j++) mnew = fmaxf(mnew, s[j]);
            float alpha = __expf(m - mnew);
            m = mnew;
            lsum *= alpha;
#pragma unroll
            for (int d = 0; d < 64; d++) o[d] *= alpha;
#pragma unroll
            for (int j = 0; j < 16; j++) {
                float p = __expf(s[j] - m);
                lsum += p;
#pragma unroll
                for (int d4 = 0; d4 < 16; d4++) {
                    float4 vv = Vs[c + j][d4];
                    o[4 * d4 + 0] += p * vv.x;
                    o[4 * d4 + 1] += p * vv.y;
                    o[4 * d4 + 2] += p * vv.z;
                    o[4 * d4 + 3] += p * vv.w;
                }
            }
        }
    }

    float rl = 1.f / lsum;
    float* op = O + (size_t)qrow * DMODEL + h * DHEAD;
#pragma unroll
    for (int i = 0; i < 16; i++) {
        float4 v = make_float4(o[4 * i + 0] * rl, o[4 * i + 1] * rl,
                               o[4 * i + 2] * rl, o[4 * i + 3] * rl);
        *reinterpret_cast<float4*>(op + 4 * i) = v;
    }
}

// ---------------- launch ---------------------------------------
extern "C" void kernel_launch(void* const* d_in, const int* in_sizes, int n_in,
                              void* d_out, int out_size) {
    const float* x  = (const float*)d_in[0];
    // d_in[1] = mask (tril) — fixed causal, hardcoded
    const float* Wq = (const float*)d_in[2];
    const float* Wk = (const float*)d_in[3];
    const float* Wv = (const float*)d_in[4];
    const float* Wo = (const float*)d_in[5];
    float* out = (float*)d_out;

    float *Qp, *Kp, *Vp, *Ap;
    cudaGetSymbolAddress((void**)&Qp, g_Q);
    cudaGetSymbolAddress((void**)&Kp, g_K);
    cudaGetSymbolAddress((void**)&Vp, g_V);
    cudaGetSymbolAddress((void**)&Ap, g_A);

    cudaFuncSetAttribute(gemm_mma_kernel,
                         cudaFuncAttributeMaxDynamicSharedMemorySize, GEMM_SMEM);

    rope_tables_kernel<<<LSEQ, 32>>>();

    dim3 ggrid(LSEQ / BM, DMODEL / BN);
    gemm_mma_kernel<<<ggrid, 256, GEMM_SMEM>>>(x, Wq, Qp);
    gemm_mma_kernel<<<ggrid, 256, GEMM_SMEM>>>(x, Wk, Kp);
    gemm_mma_kernel<<<ggrid, 256, GEMM_SMEM>>>(x, Wv, Vp);

    rope_apply_kernel<<<(LSEQ * NHEAD) / 4, 128>>>(Qp, Kp);

    dim3 fgrid(LSEQ / 128, NHEAD);
    flash_kernel<<<fgrid, 128>>>(Qp, Kp, Vp, Ap);

    gemm_mma_kernel<<<ggrid, 256, GEMM_SMEM>>>(Ap, Wo, out);
}

// round 6
// speedup vs baseline: 2.9055x; 2.2853x over previous
#include <cuda_runtime.h>
#include <cuda_bf16.h>
#include <math.h>
#include <stdint.h>

#define LSEQ 4096
#define DMODEL 1024
#define NHEAD 16
#define DHEAD 64

// ---------------- scratch (no allocations allowed) ----------------
__device__ float g_Q[LSEQ * DMODEL];
__device__ float g_K[LSEQ * DMODEL];
__device__ float g_V[LSEQ * DMODEL];
__device__ float g_A[LSEQ * DMODEL];
__device__ float g_cos[LSEQ * 32];
__device__ float g_sin[LSEQ * 32];

// =================== helpers ===================
__device__ __forceinline__ uint32_t smem_u32(const void* p) {
    uint32_t a;
    asm("{ .reg .u64 t; cvta.to.shared.u64 t, %1; cvt.u32.u64 %0, t; }"
        : "=r"(a) : "l"(p));
    return a;
}

__device__ __forceinline__ void ldsm_x4(uint32_t& r0, uint32_t& r1,
                                        uint32_t& r2, uint32_t& r3,
                                        uint32_t addr) {
    asm volatile("ldmatrix.sync.aligned.m8n8.x4.shared.b16 {%0,%1,%2,%3}, [%4];"
                 : "=r"(r0), "=r"(r1), "=r"(r2), "=r"(r3) : "r"(addr));
}

__device__ __forceinline__ void ldsm_x4_t(uint32_t& r0, uint32_t& r1,
                                          uint32_t& r2, uint32_t& r3,
                                          uint32_t addr) {
    asm volatile("ldmatrix.sync.aligned.m8n8.x4.trans.shared.b16 {%0,%1,%2,%3}, [%4];"
                 : "=r"(r0), "=r"(r1), "=r"(r2), "=r"(r3) : "r"(addr));
}

__device__ __forceinline__ void mma16816(float* d, const uint32_t* a,
                                         const uint32_t* b) {
    asm volatile(
        "mma.sync.aligned.m16n8k16.row.col.f32.bf16.bf16.f32 "
        "{%0,%1,%2,%3}, {%4,%5,%6,%7}, {%8,%9}, {%0,%1,%2,%3};"
        : "+f"(d[0]), "+f"(d[1]), "+f"(d[2]), "+f"(d[3])
        : "r"(a[0]), "r"(a[1]), "r"(a[2]), "r"(a[3]), "r"(b[0]), "r"(b[1]));
}

// fp32x4 -> bf16 hi (uint2) at sm+off, bf16 lo residual at sm+off+lo_delta
__device__ __forceinline__ void cvt_sts2(char* sm, uint32_t off,
                                         uint32_t lo_delta, float4 v) {
    __nv_bfloat162 h01 = __float22bfloat162_rn(make_float2(v.x, v.y));
    __nv_bfloat162 h23 = __float22bfloat162_rn(make_float2(v.z, v.w));
    float2 hf01 = __bfloat1622float2(h01);
    float2 hf23 = __bfloat1622float2(h23);
    __nv_bfloat162 l01 = __float22bfloat162_rn(
        make_float2(v.x - hf01.x, v.y - hf01.y));
    __nv_bfloat162 l23 = __float22bfloat162_rn(
        make_float2(v.z - hf23.x, v.w - hf23.y));
    uint2 hq, lq;
    hq.x = *reinterpret_cast<uint32_t*>(&h01);
    hq.y = *reinterpret_cast<uint32_t*>(&h23);
    lq.x = *reinterpret_cast<uint32_t*>(&l01);
    lq.y = *reinterpret_cast<uint32_t*>(&l23);
    *reinterpret_cast<uint2*>(sm + off) = hq;
    *reinterpret_cast<uint2*>(sm + off + lo_delta) = lq;
}

__device__ __forceinline__ void pack_hilo(float x, float y,
                                          uint32_t& hi, uint32_t& lo) {
    __nv_bfloat162 h = __float22bfloat162_rn(make_float2(x, y));
    float2 hf = __bfloat1622float2(h);
    __nv_bfloat162 l = __float22bfloat162_rn(make_float2(x - hf.x, y - hf.y));
    hi = *reinterpret_cast<uint32_t*>(&h);
    lo = *reinterpret_cast<uint32_t*>(&l);
}

// ======== bf16x3 HMMA GEMM: C[4096,1024] = A[4096,1024] @ B[1024,1024]^T =====
#define BM 128
#define BN 128
#define BK 32
#define ROWB 80
#define OFF_AH 0
#define OFF_AL (128 * ROWB)
#define OFF_BH (2 * 128 * ROWB)
#define OFF_BL (3 * 128 * ROWB)
#define STAGE_BYTES (4 * 128 * ROWB)
#define GEMM_SMEM (2 * STAGE_BYTES)

__global__ __launch_bounds__(256, 1) void gemm_mma_kernel(
    const float* __restrict__ A, const float* __restrict__ B,
    float* __restrict__ C) {
    extern __shared__ char smem[];
    const uint32_t sbase = smem_u32(smem);
    const int tid = threadIdx.x;
    const int wid = tid >> 5;
    const int lane = tid & 31;
    const int warp_m = wid & 3;
    const int warp_n = wid >> 2;
    const int bm = blockIdx.x * BM;
    const int bn = blockIdx.y * BN;

    float acc[2][8][4];
#pragma unroll
    for (int i = 0; i < 2; i++)
#pragma unroll
        for (int j = 0; j < 8; j++)
#pragma unroll
            for (int k = 0; k < 4; k++) acc[i][j][k] = 0.f;

    const int lrow = tid >> 1;
    const int lslot = (tid & 1) * 4;

    const int a_row = lane & 15;
    const int a_byte = (lane >> 4) << 4;
    const int b_grp = lane >> 3;
    const int b_row = (lane & 7) + ((b_grp >> 1) << 3);
    const int b_byte = (b_grp & 1) << 4;

    const float* Arow = A + (size_t)(bm + lrow) * DMODEL + lslot * 4;
    const float* Brow = B + (size_t)(bn + lrow) * DMODEL + lslot * 4;

#pragma unroll
    for (int j = 0; j < 4; j++) {
        float4 av = *reinterpret_cast<const float4*>(Arow + j * 4);
        float4 bv = *reinterpret_cast<const float4*>(Brow + j * 4);
        uint32_t off = lrow * ROWB + (lslot + j) * 8;
        cvt_sts2(smem + OFF_AH, off, OFF_AL - OFF_AH, av);
        cvt_sts2(smem + OFF_BH, off, OFF_AL - OFF_AH, bv);
    }
    __syncthreads();

    float4 va[4], vb[4];
    for (int c = 0; c < 32; c++) {
        const int cur = c & 1;
        if (c < 31) {
            const int kb = (c + 1) * BK;
#pragma unroll
            for (int j = 0; j < 4; j++) {
                va[j] = *reinterpret_cast<const float4*>(Arow + kb + j * 4);
                vb[j] = *reinterpret_cast<const float4*>(Brow + kb + j * 4);
            }
        }

        const uint32_t st = sbase + cur * STAGE_BYTES;
        const uint32_t sAh = st + OFF_AH + (warp_m * 32 + a_row) * ROWB + a_byte;
        const uint32_t sAl = st + OFF_AL + (warp_m * 32 + a_row) * ROWB + a_byte;
        const uint32_t sBh = st + OFF_BH + (warp_n * 64 + b_row) * ROWB + b_byte;
        const uint32_t sBl = st + OFF_BL + (warp_n * 64 + b_row) * ROWB + b_byte;
#pragma unroll
        for (int ks = 0; ks < 2; ks++) {
            uint32_t ah[2][4], al[2][4], bh[8][2], bl[8][2];
#pragma unroll
            for (int mt = 0; mt < 2; mt++) {
                ldsm_x4(ah[mt][0], ah[mt][1], ah[mt][2], ah[mt][3],
                        sAh + mt * 16 * ROWB + ks * 32);
                ldsm_x4(al[mt][0], al[mt][1], al[mt][2], al[mt][3],
                        sAl + mt * 16 * ROWB + ks * 32);
            }
#pragma unroll
            for (int np = 0; np < 4; np++) {
                ldsm_x4(bh[2 * np][0], bh[2 * np][1], bh[2 * np + 1][0],
                        bh[2 * np + 1][1], sBh + np * 16 * ROWB + ks * 32);
                ldsm_x4(bl[2 * np][0], bl[2 * np][1], bl[2 * np + 1][0],
                        bl[2 * np + 1][1], sBl + np * 16 * ROWB + ks * 32);
            }
#pragma unroll
            for (int mt = 0; mt < 2; mt++)
#pragma unroll
                for (int nt = 0; nt < 8; nt++) {
                    mma16816(acc[mt][nt], ah[mt], bh[nt]);
                    mma16816(acc[mt][nt], ah[mt], bl[nt]);
                    mma16816(acc[mt][nt], al[mt], bh[nt]);
                }
        }
        __syncthreads();

        if (c < 31) {
            char* sn = smem + (cur ^ 1) * STAGE_BYTES;
#pragma unroll
            for (int j = 0; j < 4; j++) {
                uint32_t off = lrow * ROWB + (lslot + j) * 8;
                cvt_sts2(sn + OFF_AH, off, OFF_AL - OFF_AH, va[j]);
                cvt_sts2(sn + OFF_BH, off, OFF_AL - OFF_AH, vb[j]);
            }
            __syncthreads();
        }
    }

#pragma unroll
    for (int mt = 0; mt < 2; mt++) {
        const int r0 = bm + warp_m * 32 + mt * 16 + (lane >> 2);
#pragma unroll
        for (int nt = 0; nt < 8; nt++) {
            const int col = bn + warp_n * 64 + nt * 8 + (lane & 3) * 2;
            *reinterpret_cast<float2*>(C + (size_t)r0 * DMODEL + col) =
                make_float2(acc[mt][nt][0], acc[mt][nt][1]);
            *reinterpret_cast<float2*>(C + (size_t)(r0 + 8) * DMODEL + col) =
                make_float2(acc[mt][nt][2], acc[mt][nt][3]);
        }
    }
}

// ---------------- RoPE tables --------------------------------
__global__ void rope_tables_kernel() {
    int l = blockIdx.x;
    int j = threadIdx.x;
    float e = (float)(2 * j) / 64.0f;
    float inv = (float)pow(10000.0, -(double)e);
    float freq = (float)l * inv;
    double s, c;
    sincos((double)freq, &s, &c);
    g_cos[l * 32 + j] = (float)c;
    g_sin[l * 32 + j] = (float)s;
}

// ---------------- RoPE apply (in place, warp per (l,h)) -------
__global__ __launch_bounds__(128) void rope_apply_kernel(float* __restrict__ Q,
                                                         float* __restrict__ K) {
    int gw = blockIdx.x * 4 + (threadIdx.x >> 5);
    int lane = threadIdx.x & 31;
    int l = gw >> 4;
    int h = gw & 15;
    float c = g_cos[l * 32 + lane];
    float s = g_sin[l * 32 + lane];
    float* q = Q + (size_t)l * DMODEL + h * DHEAD;
    float* k = K + (size_t)l * DMODEL + h * DHEAD;
    float q1 = q[2 * lane], q2 = q[2 * lane + 1];
    float k1 = k[2 * lane], k2 = k[2 * lane + 1];
    __syncwarp();
    q[lane]      = q1 * c - q2 * s;
    q[lane + 32] = q1 * s + q2 * c;
    k[lane]      = k1 * c - k2 * s;
    k[lane + 32] = k1 * s + k2 * c;
}

// ======== bf16x3 HMMA causal flash attention ========
// grid (32 qblocks, 16 heads), 256 threads = 8 warps x 16 q-rows.
// FROWB=144: 64 bf16 (128B) + 16B pad per row.
// smem 36864B: Q stage QH@0 (128x144), QL@18432. After Q frags are in regs,
// reused per key tile: KH@0, KL@9216, VH@18432, VL@27648 (64x144 each).
#define FROWB 144
#define F_QL 18432
#define F_KL 9216
#define F_VH 18432
#define F_VL 27648

__global__ __launch_bounds__(256) void flash_mma_kernel(
    const float* __restrict__ Q, const float* __restrict__ K,
    const float* __restrict__ V, float* __restrict__ O) {
    __shared__ char sm[36864];
    const uint32_t sbase = smem_u32(sm);
    const int tid = threadIdx.x;
    const int wid = tid >> 5;
    const int lane = tid & 31;
    const int qb = blockIdx.x;
    const int h = blockIdx.y;
    const int hoff = h * DHEAD;

    // ---- stage Q block (128 x 64) hi/lo ----
    {
        const int row = tid >> 1;
        const int s4 = (tid & 1) * 8;
        const float* qp = Q + (size_t)(qb * 128 + row) * DMODEL + hoff + s4 * 4;
#pragma unroll
        for (int j = 0; j < 8; j++) {
            float4 v = *reinterpret_cast<const float4*>(qp + j * 4);
            cvt_sts2(sm, (uint32_t)(row * FROWB + (s4 + j) * 8), F_QL, v);
        }
    }
    __syncthreads();

    const int frow = lane & 15;
    const int fbyte = (lane >> 4) << 4;

    uint32_t qh[4][4], ql[4][4];
    {
        const uint32_t qa = sbase + (wid * 16 + frow) * FROWB + fbyte;
#pragma unroll
        for (int ks = 0; ks < 4; ks++) {
            ldsm_x4(qh[ks][0], qh[ks][1], qh[ks][2], qh[ks][3], qa + ks * 32);
            ldsm_x4(ql[ks][0], ql[ks][1], ql[ks][2], ql[ks][3],
                    qa + F_QL + ks * 32);
        }
    }

    float o[8][4];
#pragma unroll
    for (int i = 0; i < 8; i++)
#pragma unroll
        for (int j = 0; j < 4; j++) o[i][j] = 0.f;
    float m_a = -1e30f, m_b = -1e30f, l_a = 0.f, l_b = 0.f;

    const int ncol = (lane & 3) * 2;
    const int qga = qb * 128 + wid * 16 + (lane >> 2);
    const int qgb = qga + 8;

    const int b_grp = lane >> 3;
    const int b_row = (lane & 7) + ((b_grp >> 1) << 3);
    const int b_byte = (b_grp & 1) << 4;

    const int nkt = (qb + 1) * 2;
    for (int kt = 0; kt < nkt; kt++) {
        const int kbase = kt * 64;
        __syncthreads();  // prior compute done; Q frags already in regs
        {
            const int row = tid >> 2;
            const int s4 = (tid & 3) * 4;
            const float* kp = K + (size_t)(kbase + row) * DMODEL + hoff + s4 * 4;
            const float* vp = V + (size_t)(kbase + row) * DMODEL + hoff + s4 * 4;
#pragma unroll
            for (int j = 0; j < 4; j++) {
                float4 kv = *reinterpret_cast<const float4*>(kp + j * 4);
                float4 vv = *reinterpret_cast<const float4*>(vp + j * 4);
                uint32_t off = (uint32_t)(row * FROWB + (s4 + j) * 8);
                cvt_sts2(sm, off, F_KL, kv);
                cvt_sts2(sm + F_VH, off, F_VL - F_VH, vv);
            }
        }
        __syncthreads();

        // ---- S = Q K^T (bf16x3) ----
        float s[8][4];
#pragma unroll
        for (int i = 0; i < 8; i++)
#pragma unroll
            for (int j = 0; j < 4; j++) s[i][j] = 0.f;

#pragma unroll
        for (int ks = 0; ks < 4; ks++) {
            uint32_t kf[8][2];
#pragma unroll
            for (int np = 0; np < 4; np++)
                ldsm_x4(kf[2 * np][0], kf[2 * np][1], kf[2 * np + 1][0],
                        kf[2 * np + 1][1],
                        sbase + (np * 16 + b_row) * FROWB + b_byte + ks * 32);
#pragma unroll
            for (int nt = 0; nt < 8; nt++) mma16816(s[nt], qh[ks], kf[nt]);
#pragma unroll
            for (int nt = 0; nt < 8; nt++) mma16816(s[nt], ql[ks], kf[nt]);
#pragma unroll
            for (int np = 0; np < 4; np++)
                ldsm_x4(kf[2 * np][0], kf[2 * np][1], kf[2 * np + 1][0],
                        kf[2 * np + 1][1],
                        sbase + F_KL + (np * 16 + b_row) * FROWB + b_byte + ks * 32);
#pragma unroll
            for (int nt = 0; nt < 8; nt++) mma16816(s[nt], qh[ks], kf[nt]);
        }

        // ---- scale + causal mask ----
        const bool needmask = (kbase + 63) > (qb * 128 + wid * 16);
#pragma unroll
        for (int nt = 0; nt < 8; nt++)
#pragma unroll
            for (int c = 0; c < 4; c++) {
                float sv = s[nt][c] * 0.125f;
                if (needmask) {
                    int kg = kbase + nt * 8 + ncol + (c & 1);
                    int qg = (c < 2) ? qga : qgb;
                    if (kg > qg) sv = -1e30f;
                }
                s[nt][c] = sv;
            }

        // ---- online softmax ----
        float ra = -1e30f, rb = -1e30f;
#pragma unroll
        for (int nt = 0; nt < 8; nt++) {
            ra = fmaxf(ra, fmaxf(s[nt][0], s[nt][1]));
            rb = fmaxf(rb, fmaxf(s[nt][2], s[nt][3]));
        }
        ra = fmaxf(ra, __shfl_xor_sync(0xffffffffu, ra, 1));
        ra = fmaxf(ra, __shfl_xor_sync(0xffffffffu, ra, 2));
        rb = fmaxf(rb, __shfl_xor_sync(0xffffffffu, rb, 1));
        rb = fmaxf(rb, __shfl_xor_sync(0xffffffffu, rb, 2));
        float mna = fmaxf(m_a, ra), mnb = fmaxf(m_b, rb);
        float aa = __expf(m_a - mna), ab = __expf(m_b - mnb);
        m_a = mna; m_b = mnb;
        float psa = 0.f, psb = 0.f;
#pragma unroll
        for (int nt = 0; nt < 8; nt++) {
            s[nt][0] = __expf(s[nt][0] - m_a);
            s[nt][1] = __expf(s[nt][1] - m_a);
            s[nt][2] = __expf(s[nt][2] - m_b);
            s[nt][3] = __expf(s[nt][3] - m_b);
            psa += s[nt][0] + s[nt][1];
            psb += s[nt][2] + s[nt][3];
        }
        psa += __shfl_xor_sync(0xffffffffu, psa, 1);
        psa += __shfl_xor_sync(0xffffffffu, psa, 2);
        psb += __shfl_xor_sync(0xffffffffu, psb, 1);
        psb += __shfl_xor_sync(0xffffffffu, psb, 2);
        l_a = l_a * aa + psa;
        l_b = l_b * ab + psb;
#pragma unroll
        for (int nt = 0; nt < 8; nt++) {
            o[nt][0] *= aa; o[nt][1] *= aa;
            o[nt][2] *= ab; o[nt][3] *= ab;
        }

        // ---- O += P V (bf16x3) ----
#pragma unroll
        for (int js = 0; js < 4; js++) {
            uint32_t pah[4], pal[4];
            pack_hilo(s[2 * js][0], s[2 * js][1], pah[0], pal[0]);
            pack_hilo(s[2 * js][2], s[2 * js][3], pah[1], pal[1]);
            pack_hilo(s[2 * js + 1][0], s[2 * js + 1][1], pah[2], pal[2]);
            pack_hilo(s[2 * js + 1][2], s[2 * js + 1][3], pah[3], pal[3]);

            uint32_t vf[8][2];
#pragma unroll
            for (int dp = 0; dp < 4; dp++)
                ldsm_x4_t(vf[2 * dp][0], vf[2 * dp][1], vf[2 * dp + 1][0],
                          vf[2 * dp + 1][1],
                          sbase + F_VH + (js * 16 + frow) * FROWB + dp * 32 + fbyte);
#pragma unroll
            for (int nt = 0; nt < 8; nt++) mma16816(o[nt], pah, vf[nt]);
#pragma unroll
            for (int nt = 0; nt < 8; nt++) mma16816(o[nt], pal, vf[nt]);
#pragma unroll
            for (int dp = 0; dp < 4; dp++)
                ldsm_x4_t(vf[2 * dp][0], vf[2 * dp][1], vf[2 * dp + 1][0],
                          vf[2 * dp + 1][1],
                          sbase + F_VL + (js * 16 + frow) * FROWB + dp * 32 + fbyte);
#pragma unroll
            for (int nt = 0; nt < 8; nt++) mma16816(o[nt], pah, vf[nt]);
        }
    }

    // ---- normalize + store ----
    const float rla = 1.f / l_a;
    const float rlb = 1.f / l_b;
#pragma unroll
    for (int nt = 0; nt < 8; nt++) {
        *reinterpret_cast<float2*>(O + (size_t)qga * DMODEL + hoff + nt * 8 + ncol) =
            make_float2(o[nt][0] * rla, o[nt][1] * rla);
        *reinterpret_cast<float2*>(O + (size_t)qgb * DMODEL + hoff + nt * 8 + ncol) =
            make_float2(o[nt][2] * rlb, o[nt][3] * rlb);
    }
}

// ---------------- launch ---------------------------------------
extern "C" void kernel_launch(void* const* d_in, const int* in_sizes, int n_in,
                              void* d_out, int out_size) {
    const float* x  = (const float*)d_in[0];
    // d_in[1] = mask (tril) — fixed causal, hardcoded
    const float* Wq = (const float*)d_in[2];
    const float* Wk = (const float*)d_in[3];
    const float* Wv = (const float*)d_in[4];
    const float* Wo = (const float*)d_in[5];
    float* out = (float*)d_out;

    float *Qp, *Kp, *Vp, *Ap;
    cudaGetSymbolAddress((void**)&Qp, g_Q);
    cudaGetSymbolAddress((void**)&Kp, g_K);
    cudaGetSymbolAddress((void**)&Vp, g_V);
    cudaGetSymbolAddress((void**)&Ap, g_A);

    cudaFuncSetAttribute(gemm_mma_kernel,
                         cudaFuncAttributeMaxDynamicSharedMemorySize, GEMM_SMEM);

    rope_tables_kernel<<<LSEQ, 32>>>();

    dim3 ggrid(LSEQ / BM, DMODEL / BN);
    gemm_mma_kernel<<<ggrid, 256, GEMM_SMEM>>>(x, Wq, Qp);
    gemm_mma_kernel<<<ggrid, 256, GEMM_SMEM>>>(x, Wk, Kp);
    gemm_mma_kernel<<<ggrid, 256, GEMM_SMEM>>>(x, Wv, Vp);

    rope_apply_kernel<<<(LSEQ * NHEAD) / 4, 128>>>(Qp, Kp);

    dim3 fgrid(LSEQ / 128, NHEAD);
    flash_mma_kernel<<<fgrid, 256>>>(Qp, Kp, Vp, Ap);

    gemm_mma_kernel<<<ggrid, 256, GEMM_SMEM>>>(Ap, Wo, out);
}

// round 7
// speedup vs baseline: 3.4425x; 1.1848x over previous
#include <cuda_runtime.h>
#include <cuda_bf16.h>
#include <math.h>
#include <stdint.h>

#define LSEQ 4096
#define DMODEL 1024
#define NHEAD 16
#define DHEAD 64

// ---------------- scratch (no allocations allowed) ----------------
__device__ float g_Q[LSEQ * DMODEL];
__device__ float g_K[LSEQ * DMODEL];
__device__ float g_V[LSEQ * DMODEL];
__device__ float g_A[LSEQ * DMODEL];
__device__ float g_cos[LSEQ * 32];
__device__ float g_sin[LSEQ * 32];

// =================== helpers ===================
__device__ __forceinline__ uint32_t smem_u32(const void* p) {
    uint32_t a;
    asm("{ .reg .u64 t; cvta.to.shared.u64 t, %1; cvt.u32.u64 %0, t; }"
        : "=r"(a) : "l"(p));
    return a;
}

__device__ __forceinline__ void ldsm_x4(uint32_t& r0, uint32_t& r1,
                                        uint32_t& r2, uint32_t& r3,
                                        uint32_t addr) {
    asm volatile("ldmatrix.sync.aligned.m8n8.x4.shared.b16 {%0,%1,%2,%3}, [%4];"
                 : "=r"(r0), "=r"(r1), "=r"(r2), "=r"(r3) : "r"(addr));
}

__device__ __forceinline__ void ldsm_x4_t(uint32_t& r0, uint32_t& r1,
                                          uint32_t& r2, uint32_t& r3,
                                          uint32_t addr) {
    asm volatile("ldmatrix.sync.aligned.m8n8.x4.trans.shared.b16 {%0,%1,%2,%3}, [%4];"
                 : "=r"(r0), "=r"(r1), "=r"(r2), "=r"(r3) : "r"(addr));
}

__device__ __forceinline__ void mma16816(float* d, const uint32_t* a,
                                         const uint32_t* b) {
    asm volatile(
        "mma.sync.aligned.m16n8k16.row.col.f32.bf16.bf16.f32 "
        "{%0,%1,%2,%3}, {%4,%5,%6,%7}, {%8,%9}, {%0,%1,%2,%3};"
        : "+f"(d[0]), "+f"(d[1]), "+f"(d[2]), "+f"(d[3])
        : "r"(a[0]), "r"(a[1]), "r"(a[2]), "r"(a[3]), "r"(b[0]), "r"(b[1]));
}

// fp32x4 -> bf16 hi (uint2) at sm+off, bf16 lo residual at sm+off+lo_delta
__device__ __forceinline__ void cvt_sts2(char* sm, uint32_t off,
                                         uint32_t lo_delta, float4 v) {
    __nv_bfloat162 h01 = __float22bfloat162_rn(make_float2(v.x, v.y));
    __nv_bfloat162 h23 = __float22bfloat162_rn(make_float2(v.z, v.w));
    float2 hf01 = __bfloat1622float2(h01);
    float2 hf23 = __bfloat1622float2(h23);
    __nv_bfloat162 l01 = __float22bfloat162_rn(
        make_float2(v.x - hf01.x, v.y - hf01.y));
    __nv_bfloat162 l23 = __float22bfloat162_rn(
        make_float2(v.z - hf23.x, v.w - hf23.y));
    uint2 hq, lq;
    hq.x = *reinterpret_cast<uint32_t*>(&h01);
    hq.y = *reinterpret_cast<uint32_t*>(&h23);
    lq.x = *reinterpret_cast<uint32_t*>(&l01);
    lq.y = *reinterpret_cast<uint32_t*>(&l23);
    *reinterpret_cast<uint2*>(sm + off) = hq;
    *reinterpret_cast<uint2*>(sm + off + lo_delta) = lq;
}

__device__ __forceinline__ void pack_hilo(float x, float y,
                                          uint32_t& hi, uint32_t& lo) {
    __nv_bfloat162 h = __float22bfloat162_rn(make_float2(x, y));
    float2 hf = __bfloat1622float2(h);
    __nv_bfloat162 l = __float22bfloat162_rn(make_float2(x - hf.x, y - hf.y));
    hi = *reinterpret_cast<uint32_t*>(&h);
    lo = *reinterpret_cast<uint32_t*>(&l);
}

// ======== bf16x3 HMMA GEMM: C[4096,1024] = A[4096,1024] @ B[1024,1024]^T =====
#define BM 128
#define BN 128
#define BK 32
#define ROWB 80
#define OFF_AH 0
#define OFF_AL (128 * ROWB)
#define OFF_BH (2 * 128 * ROWB)
#define OFF_BL (3 * 128 * ROWB)
#define STAGE_BYTES (4 * 128 * ROWB)
#define GEMM_SMEM (2 * STAGE_BYTES)

// shared GEMM body; B/C selected by caller
__device__ __forceinline__ void gemm_body(
    const float* __restrict__ A, const float* __restrict__ B,
    float* __restrict__ C, char* smem, int bm, int bn) {
    const uint32_t sbase = smem_u32(smem);
    const int tid = threadIdx.x;
    const int wid = tid >> 5;
    const int lane = tid & 31;
    const int warp_m = wid & 3;
    const int warp_n = wid >> 2;

    float acc[2][8][4];
#pragma unroll
    for (int i = 0; i < 2; i++)
#pragma unroll
        for (int j = 0; j < 8; j++)
#pragma unroll
            for (int k = 0; k < 4; k++) acc[i][j][k] = 0.f;

    const int lrow = tid >> 1;
    const int lslot = (tid & 1) * 4;

    const int a_row = lane & 15;
    const int a_byte = (lane >> 4) << 4;
    const int b_grp = lane >> 3;
    const int b_row = (lane & 7) + ((b_grp >> 1) << 3);
    const int b_byte = (b_grp & 1) << 4;

    const float* Arow = A + (size_t)(bm + lrow) * DMODEL + lslot * 4;
    const float* Brow = B + (size_t)(bn + lrow) * DMODEL + lslot * 4;

#pragma unroll
    for (int j = 0; j < 4; j++) {
        float4 av = *reinterpret_cast<const float4*>(Arow + j * 4);
        float4 bv = *reinterpret_cast<const float4*>(Brow + j * 4);
        uint32_t off = lrow * ROWB + (lslot + j) * 8;
        cvt_sts2(smem + OFF_AH, off, OFF_AL - OFF_AH, av);
        cvt_sts2(smem + OFF_BH, off, OFF_AL - OFF_AH, bv);
    }
    __syncthreads();

    float4 va[4], vb[4];
    for (int c = 0; c < 32; c++) {
        const int cur = c & 1;
        if (c < 31) {
            const int kb = (c + 1) * BK;
#pragma unroll
            for (int j = 0; j < 4; j++) {
                va[j] = *reinterpret_cast<const float4*>(Arow + kb + j * 4);
                vb[j] = *reinterpret_cast<const float4*>(Brow + kb + j * 4);
            }
        }

        const uint32_t st = sbase + cur * STAGE_BYTES;
        const uint32_t sAh = st + OFF_AH + (warp_m * 32 + a_row) * ROWB + a_byte;
        const uint32_t sAl = st + OFF_AL + (warp_m * 32 + a_row) * ROWB + a_byte;
        const uint32_t sBh = st + OFF_BH + (warp_n * 64 + b_row) * ROWB + b_byte;
        const uint32_t sBl = st + OFF_BL + (warp_n * 64 + b_row) * ROWB + b_byte;
#pragma unroll
        for (int ks = 0; ks < 2; ks++) {
            uint32_t ah[2][4], al[2][4], bh[8][2], bl[8][2];
#pragma unroll
            for (int mt = 0; mt < 2; mt++) {
                ldsm_x4(ah[mt][0], ah[mt][1], ah[mt][2], ah[mt][3],
                        sAh + mt * 16 * ROWB + ks * 32);
                ldsm_x4(al[mt][0], al[mt][1], al[mt][2], al[mt][3],
                        sAl + mt * 16 * ROWB + ks * 32);
            }
#pragma unroll
            for (int np = 0; np < 4; np++) {
                ldsm_x4(bh[2 * np][0], bh[2 * np][1], bh[2 * np + 1][0],
                        bh[2 * np + 1][1], sBh + np * 16 * ROWB + ks * 32);
                ldsm_x4(bl[2 * np][0], bl[2 * np][1], bl[2 * np + 1][0],
                        bl[2 * np + 1][1], sBl + np * 16 * ROWB + ks * 32);
            }
            // three passes over all 16 accumulators: RAW distance = 16
#pragma unroll
            for (int mt = 0; mt < 2; mt++)
#pragma unroll
                for (int nt = 0; nt < 8; nt++) mma16816(acc[mt][nt], ah[mt], bh[nt]);
#pragma unroll
            for (int mt = 0; mt < 2; mt++)
#pragma unroll
                for (int nt = 0; nt < 8; nt++) mma16816(acc[mt][nt], ah[mt], bl[nt]);
#pragma unroll
            for (int mt = 0; mt < 2; mt++)
#pragma unroll
                for (int nt = 0; nt < 8; nt++) mma16816(acc[mt][nt], al[mt], bh[nt]);
        }
        __syncthreads();

        if (c < 31) {
            char* sn = smem + (cur ^ 1) * STAGE_BYTES;
#pragma unroll
            for (int j = 0; j < 4; j++) {
                uint32_t off = lrow * ROWB + (lslot + j) * 8;
                cvt_sts2(sn + OFF_AH, off, OFF_AL - OFF_AH, va[j]);
                cvt_sts2(sn + OFF_BH, off, OFF_AL - OFF_AH, vb[j]);
            }
            __syncthreads();
        }
    }

#pragma unroll
    for (int mt = 0; mt < 2; mt++) {
        const int r0 = bm + warp_m * 32 + mt * 16 + (lane >> 2);
#pragma unroll
        for (int nt = 0; nt < 8; nt++) {
            const int col = bn + warp_n * 64 + nt * 8 + (lane & 3) * 2;
            *reinterpret_cast<float2*>(C + (size_t)r0 * DMODEL + col) =
                make_float2(acc[mt][nt][0], acc[mt][nt][1]);
            *reinterpret_cast<float2*>(C + (size_t)(r0 + 8) * DMODEL + col) =
                make_float2(acc[mt][nt][2], acc[mt][nt][3]);
        }
    }
}

// merged QKV: grid.z selects weight/output
__global__ __launch_bounds__(256, 1) void gemm_qkv_kernel(
    const float* __restrict__ x, const float* __restrict__ Wq,
    const float* __restrict__ Wk, const float* __restrict__ Wv) {
    extern __shared__ char smem[];
    const float* B = (blockIdx.z == 0) ? Wq : (blockIdx.z == 1) ? Wk : Wv;
    float* C = (blockIdx.z == 0) ? g_Q : (blockIdx.z == 1) ? g_K : g_V;
    gemm_body(x, B, C, smem, blockIdx.x * BM, blockIdx.y * BN);
}

__global__ __launch_bounds__(256, 1) void gemm_out_kernel(
    const float* __restrict__ Wo, float* __restrict__ out) {
    extern __shared__ char smem[];
    gemm_body(g_A, Wo, out, smem, blockIdx.x * BM, blockIdx.y * BN);
}

// ---------------- RoPE tables --------------------------------
__global__ void rope_tables_kernel() {
    int l = blockIdx.x;
    int j = threadIdx.x;
    float e = (float)(2 * j) / 64.0f;
    float inv = (float)pow(10000.0, -(double)e);
    float freq = (float)l * inv;
    double s, c;
    sincos((double)freq, &s, &c);
    g_cos[l * 32 + j] = (float)c;
    g_sin[l * 32 + j] = (float)s;
}

// ---------------- RoPE apply (in place, warp per (l,h)) -------
__global__ __launch_bounds__(128) void rope_apply_kernel(float* __restrict__ Q,
                                                         float* __restrict__ K) {
    int gw = blockIdx.x * 4 + (threadIdx.x >> 5);
    int lane = threadIdx.x & 31;
    int l = gw >> 4;
    int h = gw & 15;
    float c = g_cos[l * 32 + lane];
    float s = g_sin[l * 32 + lane];
    float* q = Q + (size_t)l * DMODEL + h * DHEAD;
    float* k = K + (size_t)l * DMODEL + h * DHEAD;
    float q1 = q[2 * lane], q2 = q[2 * lane + 1];
    float k1 = k[2 * lane], k2 = k[2 * lane + 1];
    __syncwarp();
    q[lane]      = q1 * c - q2 * s;
    q[lane + 32] = q1 * s + q2 * c;
    k[lane]      = k1 * c - k2 * s;
    k[lane + 32] = k1 * s + k2 * c;
}

// ======== bf16x3 HMMA causal flash attention ========
// grid (NHEAD, 32): x=head, y -> qb = 31 - y (heavy CTAs dispatch first).
// 256 threads = 8 warps x 16 q-rows. FROWB=144 (128B data + 16B pad).
#define FROWB 144
#define F_QL 18432
#define F_KL 9216
#define F_VH 18432
#define F_VL 27648

__global__ __launch_bounds__(256) void flash_mma_kernel(
    const float* __restrict__ Q, const float* __restrict__ K,
    const float* __restrict__ V, float* __restrict__ O) {
    __shared__ char sm[36864];
    const uint32_t sbase = smem_u32(sm);
    const int tid = threadIdx.x;
    const int wid = tid >> 5;
    const int lane = tid & 31;
    const int qb = 31 - blockIdx.y;     // heavy-first dispatch
    const int h = blockIdx.x;
    const int hoff = h * DHEAD;

    // ---- stage Q block (128 x 64) hi/lo ----
    {
        const int row = tid >> 1;
        const int s4 = (tid & 1) * 8;
        const float* qp = Q + (size_t)(qb * 128 + row) * DMODEL + hoff + s4 * 4;
#pragma unroll
        for (int j = 0; j < 8; j++) {
            float4 v = *reinterpret_cast<const float4*>(qp + j * 4);
            cvt_sts2(sm, (uint32_t)(row * FROWB + (s4 + j) * 8), F_QL, v);
        }
    }
    __syncthreads();

    const int frow = lane & 15;
    const int fbyte = (lane >> 4) << 4;

    uint32_t qh[4][4], ql[4][4];
    {
        const uint32_t qa = sbase + (wid * 16 + frow) * FROWB + fbyte;
#pragma unroll
        for (int ks = 0; ks < 4; ks++) {
            ldsm_x4(qh[ks][0], qh[ks][1], qh[ks][2], qh[ks][3], qa + ks * 32);
            ldsm_x4(ql[ks][0], ql[ks][1], ql[ks][2], ql[ks][3],
                    qa + F_QL + ks * 32);
        }
    }

    float o[8][4];
#pragma unroll
    for (int i = 0; i < 8; i++)
#pragma unroll
        for (int j = 0; j < 4; j++) o[i][j] = 0.f;
    float m_a = -1e30f, m_b = -1e30f, l_a = 0.f, l_b = 0.f;

    const int ncol = (lane & 3) * 2;
    const int qga = qb * 128 + wid * 16 + (lane >> 2);
    const int qgb = qga + 8;

    const int b_grp = lane >> 3;
    const int b_row = (lane & 7) + ((b_grp >> 1) << 3);
    const int b_byte = (b_grp & 1) << 4;

    const int nkt = (qb + 1) * 2;
    for (int kt = 0; kt < nkt; kt++) {
        const int kbase = kt * 64;
        __syncthreads();
        {
            const int row = tid >> 2;
            const int s4 = (tid & 3) * 4;
            const float* kp = K + (size_t)(kbase + row) * DMODEL + hoff + s4 * 4;
            const float* vp = V + (size_t)(kbase + row) * DMODEL + hoff + s4 * 4;
#pragma unroll
            for (int j = 0; j < 4; j++) {
                float4 kv = *reinterpret_cast<const float4*>(kp + j * 4);
                float4 vv = *reinterpret_cast<const float4*>(vp + j * 4);
                uint32_t off = (uint32_t)(row * FROWB + (s4 + j) * 8);
                cvt_sts2(sm, off, F_KL, kv);
                cvt_sts2(sm + F_VH, off, F_VL - F_VH, vv);
            }
        }
        __syncthreads();

        // ---- S = Q K^T (bf16x3) ----
        float s[8][4];
#pragma unroll
        for (int i = 0; i < 8; i++)
#pragma unroll
            for (int j = 0; j < 4; j++) s[i][j] = 0.f;

#pragma unroll
        for (int ks = 0; ks < 4; ks++) {
            uint32_t kf[8][2];
#pragma unroll
            for (int np = 0; np < 4; np++)
                ldsm_x4(kf[2 * np][0], kf[2 * np][1], kf[2 * np + 1][0],
                        kf[2 * np + 1][1],
                        sbase + (np * 16 + b_row) * FROWB + b_byte + ks * 32);
#pragma unroll
            for (int nt = 0; nt < 8; nt++) mma16816(s[nt], qh[ks], kf[nt]);
#pragma unroll
            for (int nt = 0; nt < 8; nt++) mma16816(s[nt], ql[ks], kf[nt]);
#pragma unroll
            for (int np = 0; np < 4; np++)
                ldsm_x4(kf[2 * np][0], kf[2 * np][1], kf[2 * np + 1][0],
                        kf[2 * np + 1][1],
                        sbase + F_KL + (np * 16 + b_row) * FROWB + b_byte + ks * 32);
#pragma unroll
            for (int nt = 0; nt < 8; nt++) mma16816(s[nt], qh[ks], kf[nt]);
        }

        // ---- scale + causal mask ----
        const bool needmask = (kbase + 63) > (qb * 128 + wid * 16);
#pragma unroll
        for (int nt = 0; nt < 8; nt++)
#pragma unroll
            for (int c = 0; c < 4; c++) {
                float sv = s[nt][c] * 0.125f;
                if (needmask) {
                    int kg = kbase + nt * 8 + ncol + (c & 1);
                    int qg = (c < 2) ? qga : qgb;
                    if (kg > qg) sv = -1e30f;
                }
                s[nt][c] = sv;
            }

        // ---- online softmax ----
        float ra = -1e30f, rb = -1e30f;
#pragma unroll
        for (int nt = 0; nt < 8; nt++) {
            ra = fmaxf(ra, fmaxf(s[nt][0], s[nt][1]));
            rb = fmaxf(rb, fmaxf(s[nt][2], s[nt][3]));
        }
        ra = fmaxf(ra, __shfl_xor_sync(0xffffffffu, ra, 1));
        ra = fmaxf(ra, __shfl_xor_sync(0xffffffffu, ra, 2));
        rb = fmaxf(rb, __shfl_xor_sync(0xffffffffu, rb, 1));
        rb = fmaxf(rb, __shfl_xor_sync(0xffffffffu, rb, 2));
        float mna = fmaxf(m_a, ra), mnb = fmaxf(m_b, rb);
        float aa = __expf(m_a - mna), ab = __expf(m_b - mnb);
        m_a = mna; m_b = mnb;
        float psa = 0.f, psb = 0.f;
#pragma unroll
        for (int nt = 0; nt < 8; nt++) {
            s[nt][0] = __expf(s[nt][0] - m_a);
            s[nt][1] = __expf(s[nt][1] - m_a);
            s[nt][2] = __expf(s[nt][2] - m_b);
            s[nt][3] = __expf(s[nt][3] - m_b);
            psa += s[nt][0] + s[nt][1];
            psb += s[nt][2] + s[nt][3];
        }
        psa += __shfl_xor_sync(0xffffffffu, psa, 1);
        psa += __shfl_xor_sync(0xffffffffu, psa, 2);
        psb += __shfl_xor_sync(0xffffffffu, psb, 1);
        psb += __shfl_xor_sync(0xffffffffu, psb, 2);
        l_a = l_a * aa + psa;
        l_b = l_b * ab + psb;
#pragma unroll
        for (int nt = 0; nt < 8; nt++) {
            o[nt][0] *= aa; o[nt][1] *= aa;
            o[nt][2] *= ab; o[nt][3] *= ab;
        }

        // ---- O += P V (bf16x3) ----
#pragma unroll
        for (int js = 0; js < 4; js++) {
            uint32_t pah[4], pal[4];
            pack_hilo(s[2 * js][0], s[2 * js][1], pah[0], pal[0]);
            pack_hilo(s[2 * js][2], s[2 * js][3], pah[1], pal[1]);
            pack_hilo(s[2 * js + 1][0], s[2 * js + 1][1], pah[2], pal[2]);
            pack_hilo(s[2 * js + 1][2], s[2 * js + 1][3], pah[3], pal[3]);

            uint32_t vf[8][2];
#pragma unroll
            for (int dp = 0; dp < 4; dp++)
                ldsm_x4_t(vf[2 * dp][0], vf[2 * dp][1], vf[2 * dp + 1][0],
                          vf[2 * dp + 1][1],
                          sbase + F_VH + (js * 16 + frow) * FROWB + dp * 32 + fbyte);
#pragma unroll
            for (int nt = 0; nt < 8; nt++) mma16816(o[nt], pah, vf[nt]);
#pragma unroll
            for (int nt = 0; nt < 8; nt++) mma16816(o[nt], pal, vf[nt]);
#pragma unroll
            for (int dp = 0; dp < 4; dp++)
                ldsm_x4_t(vf[2 * dp][0], vf[2 * dp][1], vf[2 * dp + 1][0],
                          vf[2 * dp + 1][1],
                          sbase + F_VL + (js * 16 + frow) * FROWB + dp * 32 + fbyte);
#pragma unroll
            for (int nt = 0; nt < 8; nt++) mma16816(o[nt], pah, vf[nt]);
        }
    }

    // ---- normalize + store ----
    const float rla = 1.f / l_a;
    const float rlb = 1.f / l_b;
#pragma unroll
    for (int nt = 0; nt < 8; nt++) {
        *reinterpret_cast<float2*>(O + (size_t)qga * DMODEL + hoff + nt * 8 + ncol) =
            make_float2(o[nt][0] * rla, o[nt][1] * rla);
        *reinterpret_cast<float2*>(O + (size_t)qgb * DMODEL + hoff + nt * 8 + ncol) =
            make_float2(o[nt][2] * rlb, o[nt][3] * rlb);
    }
}

// ---------------- launch ---------------------------------------
extern "C" void kernel_launch(void* const* d_in, const int* in_sizes, int n_in,
                              void* d_out, int out_size) {
    const float* x  = (const float*)d_in[0];
    // d_in[1] = mask (tril) — fixed causal, hardcoded
    const float* Wq = (const float*)d_in[2];
    const float* Wk = (const float*)d_in[3];
    const float* Wv = (const float*)d_in[4];
    const float* Wo = (const float*)d_in[5];
    float* out = (float*)d_out;

    float *Qp, *Kp, *Vp, *Ap;
    cudaGetSymbolAddress((void**)&Qp, g_Q);
    cudaGetSymbolAddress((void**)&Kp, g_K);
    cudaGetSymbolAddress((void**)&Vp, g_V);
    cudaGetSymbolAddress((void**)&Ap, g_A);

    cudaFuncSetAttribute(gemm_qkv_kernel,
                         cudaFuncAttributeMaxDynamicSharedMemorySize, GEMM_SMEM);
    cudaFuncSetAttribute(gemm_out_kernel,
                         cudaFuncAttributeMaxDynamicSharedMemorySize, GEMM_SMEM);

    rope_tables_kernel<<<LSEQ, 32>>>();

    dim3 qkvgrid(LSEQ / BM, DMODEL / BN, 3);
    gemm_qkv_kernel<<<qkvgrid, 256, GEMM_SMEM>>>(x, Wq, Wk, Wv);

    rope_apply_kernel<<<(LSEQ * NHEAD) / 4, 128>>>(Qp, Kp);

    dim3 fgrid(NHEAD, LSEQ / 128);
    flash_mma_kernel<<<fgrid, 256>>>(Qp, Kp, Vp, Ap);

    dim3 ogrid(LSEQ / BM, DMODEL / BN);
    gemm_out_kernel<<<ogrid, 256, GEMM_SMEM>>>(Wo, out);
}

// round 9
// speedup vs baseline: 3.6532x; 1.0612x over previous
#include <cuda_runtime.h>
#include <cuda_bf16.h>
#include <math.h>
#include <stdint.h>

#define LSEQ 4096
#define DMODEL 1024
#define NHEAD 16
#define DHEAD 64

// ---------------- scratch (no allocations allowed) ----------------
__device__ float g_Q[LSEQ * DMODEL];
__device__ float g_K[LSEQ * DMODEL];
__device__ float g_V[LSEQ * DMODEL];
__device__ float g_A[LSEQ * DMODEL];
__device__ float g_cos[LSEQ * 32];
__device__ float g_sin[LSEQ * 32];

// =================== helpers ===================
__device__ __forceinline__ uint32_t smem_u32(const void* p) {
    uint32_t a;
    asm("{ .reg .u64 t; cvta.to.shared.u64 t, %1; cvt.u32.u64 %0, t; }"
        : "=r"(a) : "l"(p));
    return a;
}

__device__ __forceinline__ void ldsm_x4(uint32_t& r0, uint32_t& r1,
                                        uint32_t& r2, uint32_t& r3,
                                        uint32_t addr) {
    asm volatile("ldmatrix.sync.aligned.m8n8.x4.shared.b16 {%0,%1,%2,%3}, [%4];"
                 : "=r"(r0), "=r"(r1), "=r"(r2), "=r"(r3) : "r"(addr));
}

__device__ __forceinline__ void ldsm_x4_t(uint32_t& r0, uint32_t& r1,
                                          uint32_t& r2, uint32_t& r3,
                                          uint32_t addr) {
    asm volatile("ldmatrix.sync.aligned.m8n8.x4.trans.shared.b16 {%0,%1,%2,%3}, [%4];"
                 : "=r"(r0), "=r"(r1), "=r"(r2), "=r"(r3) : "r"(addr));
}

__device__ __forceinline__ void mma16816(float* d, const uint32_t* a,
                                         const uint32_t* b) {
    asm volatile(
        "mma.sync.aligned.m16n8k16.row.col.f32.bf16.bf16.f32 "
        "{%0,%1,%2,%3}, {%4,%5,%6,%7}, {%8,%9}, {%0,%1,%2,%3};"
        : "+f"(d[0]), "+f"(d[1]), "+f"(d[2]), "+f"(d[3])
        : "r"(a[0]), "r"(a[1]), "r"(a[2]), "r"(a[3]), "r"(b[0]), "r"(b[1]));
}

// fp32x4 -> bf16 hi (uint2) at sm+off, bf16 lo residual at sm+off+lo_delta
__device__ __forceinline__ void cvt_sts2(char* sm, uint32_t off,
                                         uint32_t lo_delta, float4 v) {
    __nv_bfloat162 h01 = __float22bfloat162_rn(make_float2(v.x, v.y));
    __nv_bfloat162 h23 = __float22bfloat162_rn(make_float2(v.z, v.w));
    float2 hf01 = __bfloat1622float2(h01);
    float2 hf23 = __bfloat1622float2(h23);
    __nv_bfloat162 l01 = __float22bfloat162_rn(
        make_float2(v.x - hf01.x, v.y - hf01.y));
    __nv_bfloat162 l23 = __float22bfloat162_rn(
        make_float2(v.z - hf23.x, v.w - hf23.y));
    uint2 hq, lq;
    hq.x = *reinterpret_cast<uint32_t*>(&h01);
    hq.y = *reinterpret_cast<uint32_t*>(&h23);
    lq.x = *reinterpret_cast<uint32_t*>(&l01);
    lq.y = *reinterpret_cast<uint32_t*>(&l23);
    *reinterpret_cast<uint2*>(sm + off) = hq;
    *reinterpret_cast<uint2*>(sm + off + lo_delta) = lq;
}

__device__ __forceinline__ void pack_hilo(float x, float y,
                                          uint32_t& hi, uint32_t& lo) {
    __nv_bfloat162 h = __float22bfloat162_rn(make_float2(x, y));
    float2 hf = __bfloat1622float2(h);
    __nv_bfloat162 l = __float22bfloat162_rn(make_float2(x - hf.x, y - hf.y));
    hi = *reinterpret_cast<uint32_t*>(&h);
    lo = *reinterpret_cast<uint32_t*>(&l);
}

// ======== bf16x3 HMMA GEMM: C[4096,1024] = A[4096,1024] @ B[1024,1024]^T =====
#define BM 128
#define BN 128
#define BK 32
#define ROWB 80
#define OFF_AH 0
#define OFF_AL (128 * ROWB)
#define OFF_BH (2 * 128 * ROWB)
#define OFF_BL (3 * 128 * ROWB)
#define STAGE_BYTES (4 * 128 * ROWB)
#define GEMM_SMEM (2 * STAGE_BYTES)

__device__ __forceinline__ void gemm_body(
    const float* __restrict__ A, const float* __restrict__ B,
    float* __restrict__ C, char* smem, int bm, int bn) {
    const uint32_t sbase = smem_u32(smem);
    const int tid = threadIdx.x;
    const int wid = tid >> 5;
    const int lane = tid & 31;
    const int warp_m = wid & 3;
    const int warp_n = wid >> 2;

    float acc[2][8][4];
#pragma unroll
    for (int i = 0; i < 2; i++)
#pragma unroll
        for (int j = 0; j < 8; j++)
#pragma unroll
            for (int k = 0; k < 4; k++) acc[i][j][k] = 0.f;

    const int lrow = tid >> 1;
    const int lslot = (tid & 1) * 4;

    const int a_row = lane & 15;
    const int a_byte = (lane >> 4) << 4;
    const int b_grp = lane >> 3;
    const int b_row = (lane & 7) + ((b_grp >> 1) << 3);
    const int b_byte = (b_grp & 1) << 4;

    const float* Arow = A + (size_t)(bm + lrow) * DMODEL + lslot * 4;
    const float* Brow = B + (size_t)(bn + lrow) * DMODEL + lslot * 4;

#pragma unroll
    for (int j = 0; j < 4; j++) {
        float4 av = *reinterpret_cast<const float4*>(Arow + j * 4);
        float4 bv = *reinterpret_cast<const float4*>(Brow + j * 4);
        uint32_t off = lrow * ROWB + (lslot + j) * 8;
        cvt_sts2(smem + OFF_AH, off, OFF_AL - OFF_AH, av);
        cvt_sts2(smem + OFF_BH, off, OFF_AL - OFF_AH, bv);
    }
    __syncthreads();

    float4 va[4], vb[4];
    for (int c = 0; c < 32; c++) {
        const int cur = c & 1;
        if (c < 31) {
            const int kb = (c + 1) * BK;
#pragma unroll
            for (int j = 0; j < 4; j++) {
                va[j] = *reinterpret_cast<const float4*>(Arow + kb + j * 4);
                vb[j] = *reinterpret_cast<const float4*>(Brow + kb + j * 4);
            }
        }

        const uint32_t st = sbase + cur * STAGE_BYTES;
        const uint32_t sAh = st + OFF_AH + (warp_m * 32 + a_row) * ROWB + a_byte;
        const uint32_t sAl = st + OFF_AL + (warp_m * 32 + a_row) * ROWB + a_byte;
        const uint32_t sBh = st + OFF_BH + (warp_n * 64 + b_row) * ROWB + b_byte;
        const uint32_t sBl = st + OFF_BL + (warp_n * 64 + b_row) * ROWB + b_byte;
#pragma unroll
        for (int ks = 0; ks < 2; ks++) {
            uint32_t ah[2][4], al[2][4], bh[8][2], bl[8][2];
#pragma unroll
            for (int mt = 0; mt < 2; mt++) {
                ldsm_x4(ah[mt][0], ah[mt][1], ah[mt][2], ah[mt][3],
                        sAh + mt * 16 * ROWB + ks * 32);
                ldsm_x4(al[mt][0], al[mt][1], al[mt][2], al[mt][3],
                        sAl + mt * 16 * ROWB + ks * 32);
            }
#pragma unroll
            for (int np = 0; np < 4; np++) {
                ldsm_x4(bh[2 * np][0], bh[2 * np][1], bh[2 * np + 1][0],
                        bh[2 * np + 1][1], sBh + np * 16 * ROWB + ks * 32);
                ldsm_x4(bl[2 * np][0], bl[2 * np][1], bl[2 * np + 1][0],
                        bl[2 * np + 1][1], sBl + np * 16 * ROWB + ks * 32);
            }
#pragma unroll
            for (int mt = 0; mt < 2; mt++)
#pragma unroll
                for (int nt = 0; nt < 8; nt++) mma16816(acc[mt][nt], ah[mt], bh[nt]);
#pragma unroll
            for (int mt = 0; mt < 2; mt++)
#pragma unroll
                for (int nt = 0; nt < 8; nt++) mma16816(acc[mt][nt], ah[mt], bl[nt]);
#pragma unroll
            for (int mt = 0; mt < 2; mt++)
#pragma unroll
                for (int nt = 0; nt < 8; nt++) mma16816(acc[mt][nt], al[mt], bh[nt]);
        }
        __syncthreads();

        if (c < 31) {
            char* sn = smem + (cur ^ 1) * STAGE_BYTES;
#pragma unroll
            for (int j = 0; j < 4; j++) {
                uint32_t off = lrow * ROWB + (lslot + j) * 8;
                cvt_sts2(sn + OFF_AH, off, OFF_AL - OFF_AH, va[j]);
                cvt_sts2(sn + OFF_BH, off, OFF_AL - OFF_AH, vb[j]);
            }
            __syncthreads();
        }
    }

#pragma unroll
    for (int mt = 0; mt < 2; mt++) {
        const int r0 = bm + warp_m * 32 + mt * 16 + (lane >> 2);
#pragma unroll
        for (int nt = 0; nt < 8; nt++) {
            const int col = bn + warp_n * 64 + nt * 8 + (lane & 3) * 2;
            *reinterpret_cast<float2*>(C + (size_t)r0 * DMODEL + col) =
                make_float2(acc[mt][nt][0], acc[mt][nt][1]);
            *reinterpret_cast<float2*>(C + (size_t)(r0 + 8) * DMODEL + col) =
                make_float2(acc[mt][nt][2], acc[mt][nt][3]);
        }
    }
}

__global__ __launch_bounds__(256, 1) void gemm_qkv_kernel(
    const float* __restrict__ x, const float* __restrict__ Wq,
    const float* __restrict__ Wk, const float* __restrict__ Wv) {
    extern __shared__ char smem[];
    const float* B = (blockIdx.z == 0) ? Wq : (blockIdx.z == 1) ? Wk : Wv;
    float* C = (blockIdx.z == 0) ? g_Q : (blockIdx.z == 1) ? g_K : g_V;
    gemm_body(x, B, C, smem, blockIdx.x * BM, blockIdx.y * BN);
}

__global__ __launch_bounds__(256, 1) void gemm_out_kernel(
    const float* __restrict__ Wo, float* __restrict__ out) {
    extern __shared__ char smem[];
    gemm_body(g_A, Wo, out, smem, blockIdx.x * BM, blockIdx.y * BN);
}

// ---------------- RoPE tables --------------------------------
__global__ void rope_tables_kernel() {
    int l = blockIdx.x;
    int j = threadIdx.x;
    float e = (float)(2 * j) / 64.0f;
    float inv = (float)pow(10000.0, -(double)e);
    float freq = (float)l * inv;
    double s, c;
    sincos((double)freq, &s, &c);
    g_cos[l * 32 + j] = (float)c;
    g_sin[l * 32 + j] = (float)s;
}

// ---------------- RoPE apply (in place, warp per (l,h)) -------
__global__ __launch_bounds__(128) void rope_apply_kernel(float* __restrict__ Q,
                                                         float* __restrict__ K) {
    int gw = blockIdx.x * 4 + (threadIdx.x >> 5);
    int lane = threadIdx.x & 31;
    int l = gw >> 4;
    int h = gw & 15;
    float c = g_cos[l * 32 + lane];
    float s = g_sin[l * 32 + lane];
    float* q = Q + (size_t)l * DMODEL + h * DHEAD;
    float* k = K + (size_t)l * DMODEL + h * DHEAD;
    float q1 = q[2 * lane], q2 = q[2 * lane + 1];
    float k1 = k[2 * lane], k2 = k[2 * lane + 1];
    __syncwarp();
    q[lane]      = q1 * c - q2 * s;
    q[lane + 32] = q1 * s + q2 * c;
    k[lane]      = k1 * c - k2 * s;
    k[lane + 32] = k1 * s + k2 * c;
}

// ======== bf16x3 HMMA causal flash attention (pipelined K/V) ========
// grid (NHEAD, 32): qb = 31 - blockIdx.y (heavy-first).
// DYNAMIC smem 73728B = 2 buffers of 36864. Within a buffer: KH@0, KL@9216,
// VH@18432, VL@27648 (64 rows x FROWB). Q stages into buffer 0 (QH@0,
// QL@18432) before tile 0 overwrites it.
#define FROWB 144
#define FBUF 36864
#define F_KL 9216
#define F_VH 18432
#define F_VL 27648
#define FLASH_SMEM (2 * FBUF)

__global__ __launch_bounds__(256) void flash_mma_kernel(
    const float* __restrict__ Q, const float* __restrict__ K,
    const float* __restrict__ V, float* __restrict__ O) {
    extern __shared__ char sm[];
    const uint32_t sbase = smem_u32(sm);
    const int tid = threadIdx.x;
    const int wid = tid >> 5;
    const int lane = tid & 31;
    const int qb = 31 - blockIdx.y;
    const int h = blockIdx.x;
    const int hoff = h * DHEAD;

    // ---- stage Q block (128 x 64) hi/lo into buffer 0 ----
    {
        const int row = tid >> 1;
        const int s4 = (tid & 1) * 8;
        const float* qp = Q + (size_t)(qb * 128 + row) * DMODEL + hoff + s4 * 4;
#pragma unroll
        for (int j = 0; j < 8; j++) {
            float4 v = *reinterpret_cast<const float4*>(qp + j * 4);
            cvt_sts2(sm, (uint32_t)(row * FROWB + (s4 + j) * 8), 18432u, v);
        }
    }
    __syncthreads();

    const int frow = lane & 15;
    const int fbyte = (lane >> 4) << 4;

    uint32_t qh[4][4], ql[4][4];
    {
        const uint32_t qa = sbase + (wid * 16 + frow) * FROWB + fbyte;
#pragma unroll
        for (int ks = 0; ks < 4; ks++) {
            ldsm_x4(qh[ks][0], qh[ks][1], qh[ks][2], qh[ks][3], qa + ks * 32);
            ldsm_x4(ql[ks][0], ql[ks][1], ql[ks][2], ql[ks][3],
                    qa + 18432 + ks * 32);
        }
    }
    __syncthreads();   // all Q frag reads complete before buffer 0 reuse

    // loader coords: row = tid>>2, float4 slots ks4..ks4+3 (consecutive)
    const int krow = tid >> 2;
    const int ks4 = (tid & 3) * 4;
    const float* Kp = K + (size_t)krow * DMODEL + hoff + ks4 * 4;
    const float* Vp = V + (size_t)krow * DMODEL + hoff + ks4 * 4;
    const uint32_t soff = (uint32_t)(krow * FROWB + ks4 * 8);

    // ---- tile 0 into buffer 0 ----
#pragma unroll
    for (int j = 0; j < 4; j++) {
        float4 kv = *reinterpret_cast<const float4*>(Kp + j * 4);
        float4 vv = *reinterpret_cast<const float4*>(Vp + j * 4);
        cvt_sts2(sm, soff + j * 8, F_KL, kv);
        cvt_sts2(sm + F_VH, soff + j * 8, F_VL - F_VH, vv);
    }
    __syncthreads();

    float o[8][4];
#pragma unroll
    for (int i = 0; i < 8; i++)
#pragma unroll
        for (int j = 0; j < 4; j++) o[i][j] = 0.f;
    float m_a = -1e30f, m_b = -1e30f, l_a = 0.f, l_b = 0.f;

    const int ncol = (lane & 3) * 2;
    const int qga = qb * 128 + wid * 16 + (lane >> 2);
    const int qgb = qga + 8;

    const int b_grp = lane >> 3;
    const int b_row = (lane & 7) + ((b_grp >> 1) << 3);
    const int b_byte = (b_grp & 1) << 4;

    const int nkt = (qb + 1) * 2;
    float4 pk[4], pv[4];
    for (int kt = 0; kt < nkt; kt++) {
        const int kbase = kt * 64;
        const uint32_t bb = sbase + (uint32_t)(kt & 1) * FBUF;

        // ---- prefetch next tile into registers (overlaps compute) ----
        if (kt + 1 < nkt) {
            const size_t nb = (size_t)(kbase + 64) * DMODEL;
#pragma unroll
            for (int j = 0; j < 4; j++) {
                pk[j] = *reinterpret_cast<const float4*>(Kp + nb + j * 4);
                pv[j] = *reinterpret_cast<const float4*>(Vp + nb + j * 4);
            }
        }

        // ---- S = Q K^T (bf16x3) ----
        float s[8][4];
#pragma unroll
        for (int i = 0; i < 8; i++)
#pragma unroll
            for (int j = 0; j < 4; j++) s[i][j] = 0.f;

#pragma unroll
        for (int ks = 0; ks < 4; ks++) {
            uint32_t kf[8][2];
#pragma unroll
            for (int np = 0; np < 4; np++)
                ldsm_x4(kf[2 * np][0], kf[2 * np][1], kf[2 * np + 1][0],
                        kf[2 * np + 1][1],
                        bb + (np * 16 + b_row) * FROWB + b_byte + ks * 32);
#pragma unroll
            for (int nt = 0; nt < 8; nt++) mma16816(s[nt], qh[ks], kf[nt]);
#pragma unroll
            for (int nt = 0; nt < 8; nt++) mma16816(s[nt], ql[ks], kf[nt]);
#pragma unroll
            for (int np = 0; np < 4; np++)
                ldsm_x4(kf[2 * np][0], kf[2 * np][1], kf[2 * np + 1][0],
                        kf[2 * np + 1][1],
                        bb + F_KL + (np * 16 + b_row) * FROWB + b_byte + ks * 32);
#pragma unroll
            for (int nt = 0; nt < 8; nt++) mma16816(s[nt], qh[ks], kf[nt]);
        }

        // ---- scale + causal mask ----
        const bool needmask = (kbase + 63) > (qb * 128 + wid * 16);
#pragma unroll
        for (int nt = 0; nt < 8; nt++)
#pragma unroll
            for (int c = 0; c < 4; c++) {
                float sv = s[nt][c] * 0.125f;
                if (needmask) {
                    int kg = kbase + nt * 8 + ncol + (c & 1);
                    int qg = (c < 2) ? qga : qgb;
                    if (kg > qg) sv = -1e30f;
                }
                s[nt][c] = sv;
            }

        // ---- online softmax ----
        float ra = -1e30f, rb = -1e30f;
#pragma unroll
        for (int nt = 0; nt < 8; nt++) {
            ra = fmaxf(ra, fmaxf(s[nt][0], s[nt][1]));
            rb = fmaxf(rb, fmaxf(s[nt][2], s[nt][3]));
        }
        ra = fmaxf(ra, __shfl_xor_sync(0xffffffffu, ra, 1));
        ra = fmaxf(ra, __shfl_xor_sync(0xffffffffu, ra, 2));
        rb = fmaxf(rb, __shfl_xor_sync(0xffffffffu, rb, 1));
        rb = fmaxf(rb, __shfl_xor_sync(0xffffffffu, rb, 2));
        float mna = fmaxf(m_a, ra), mnb = fmaxf(m_b, rb);
        float aa = __expf(m_a - mna), ab = __expf(m_b - mnb);
        m_a = mna; m_b = mnb;
        float psa = 0.f, psb = 0.f;
#pragma unroll
        for (int nt = 0; nt < 8; nt++) {
            s[nt][0] = __expf(s[nt][0] - m_a);
            s[nt][1] = __expf(s[nt][1] - m_a);
            s[nt][2] = __expf(s[nt][2] - m_b);
            s[nt][3] = __expf(s[nt][3] - m_b);
            psa += s[nt][0] + s[nt][1];
            psb += s[nt][2] + s[nt][3];
        }
        psa += __shfl_xor_sync(0xffffffffu, psa, 1);
        psa += __shfl_xor_sync(0xffffffffu, psa, 2);
        psb += __shfl_xor_sync(0xffffffffu, psb, 1);
        psb += __shfl_xor_sync(0xffffffffu, psb, 2);
        l_a = l_a * aa + psa;
        l_b = l_b * ab + psb;
#pragma unroll
        for (int nt = 0; nt < 8; nt++) {
            o[nt][0] *= aa; o[nt][1] *= aa;
            o[nt][2] *= ab; o[nt][3] *= ab;
        }

        // ---- O += P V (bf16x3) ----
#pragma unroll
        for (int js = 0; js < 4; js++) {
            uint32_t pah[4], pal[4];
            pack_hilo(s[2 * js][0], s[2 * js][1], pah[0], pal[0]);
            pack_hilo(s[2 * js][2], s[2 * js][3], pah[1], pal[1]);
            pack_hilo(s[2 * js + 1][0], s[2 * js + 1][1], pah[2], pal[2]);
            pack_hilo(s[2 * js + 1][2], s[2 * js + 1][3], pah[3], pal[3]);

            uint32_t vf[8][2];
#pragma unroll
            for (int dp = 0; dp < 4; dp++)
                ldsm_x4_t(vf[2 * dp][0], vf[2 * dp][1], vf[2 * dp + 1][0],
                          vf[2 * dp + 1][1],
                          bb + F_VH + (js * 16 + frow) * FROWB + dp * 32 + fbyte);
#pragma unroll
            for (int nt = 0; nt < 8; nt++) mma16816(o[nt], pah, vf[nt]);
#pragma unroll
            for (int nt = 0; nt < 8; nt++) mma16816(o[nt], pal, vf[nt]);
#pragma unroll
            for (int dp = 0; dp < 4; dp++)
                ldsm_x4_t(vf[2 * dp][0], vf[2 * dp][1], vf[2 * dp + 1][0],
                          vf[2 * dp + 1][1],
                          bb + F_VL + (js * 16 + frow) * FROWB + dp * 32 + fbyte);
#pragma unroll
            for (int nt = 0; nt < 8; nt++) mma16816(o[nt], pah, vf[nt]);
        }

        // ---- store prefetched tile to alternate buffer ----
        if (kt + 1 < nkt) {
            char* nbuf = sm + ((kt + 1) & 1) * FBUF;
#pragma unroll
            for (int j = 0; j < 4; j++) {
                cvt_sts2(nbuf, soff + j * 8, F_KL, pk[j]);
                cvt_sts2(nbuf + F_VH, soff + j * 8, F_VL - F_VH, pv[j]);
            }
        }
        __syncthreads();
    }

    // ---- normalize + store ----
    const float rla = 1.f / l_a;
    const float rlb = 1.f / l_b;
#pragma unroll
    for (int nt = 0; nt < 8; nt++) {
        *reinterpret_cast<float2*>(O + (size_t)qga * DMODEL + hoff + nt * 8 + ncol) =
            make_float2(o[nt][0] * rla, o[nt][1] * rla);
        *reinterpret_cast<float2*>(O + (size_t)qgb * DMODEL + hoff + nt * 8 + ncol) =
            make_float2(o[nt][2] * rlb, o[nt][3] * rlb);
    }
}

// ---------------- launch ---------------------------------------
extern "C" void kernel_launch(void* const* d_in, const int* in_sizes, int n_in,
                              void* d_out, int out_size) {
    const float* x  = (const float*)d_in[0];
    // d_in[1] = mask (tril) — fixed causal, hardcoded
    const float* Wq = (const float*)d_in[2];
    const float* Wk = (const float*)d_in[3];
    const float* Wv = (const float*)d_in[4];
    const float* Wo = (const float*)d_in[5];
    float* out = (float*)d_out;

    float *Qp, *Kp, *Vp, *Ap;
    cudaGetSymbolAddress((void**)&Qp, g_Q);
    cudaGetSymbolAddress((void**)&Kp, g_K);
    cudaGetSymbolAddress((void**)&Vp, g_V);
    cudaGetSymbolAddress((void**)&Ap, g_A);

    cudaFuncSetAttribute(gemm_qkv_kernel,
                         cudaFuncAttributeMaxDynamicSharedMemorySize, GEMM_SMEM);
    cudaFuncSetAttribute(gemm_out_kernel,
                         cudaFuncAttributeMaxDynamicSharedMemorySize, GEMM_SMEM);
    cudaFuncSetAttribute(flash_mma_kernel,
                         cudaFuncAttributeMaxDynamicSharedMemorySize, FLASH_SMEM);

    rope_tables_kernel<<<LSEQ, 32>>>();

    dim3 qkvgrid(LSEQ / BM, DMODEL / BN, 3);
    gemm_qkv_kernel<<<qkvgrid, 256, GEMM_SMEM>>>(x, Wq, Wk, Wv);

    rope_apply_kernel<<<(LSEQ * NHEAD) / 4, 128>>>(Qp, Kp);

    dim3 fgrid(NHEAD, LSEQ / 128);
    flash_mma_kernel<<<fgrid, 256, FLASH_SMEM>>>(Qp, Kp, Vp, Ap);

    dim3 ogrid(LSEQ / BM, DMODEL / BN);
    gemm_out_kernel<<<ogrid, 256, GEMM_SMEM>>>(Wo, out);
}

// round 10
// speedup vs baseline: 3.7955x; 1.0390x over previous
#include <cuda_runtime.h>
#include <cuda_bf16.h>
#include <math.h>
#include <stdint.h>

#define LSEQ 4096
#define DMODEL 1024
#define NHEAD 16
#define DHEAD 64
#define DSQ (DMODEL * DMODEL)

// ---------------- scratch (no allocations allowed) ----------------
__device__ float g_Q[LSEQ * DMODEL];
__device__ float g_K[LSEQ * DMODEL];
__device__ __nv_bfloat16 g_xh[LSEQ * DMODEL], g_xl[LSEQ * DMODEL];
__device__ __nv_bfloat16 g_qh[LSEQ * DMODEL], g_ql[LSEQ * DMODEL];
__device__ __nv_bfloat16 g_kh[LSEQ * DMODEL], g_kl[LSEQ * DMODEL];
__device__ __nv_bfloat16 g_vh[LSEQ * DMODEL], g_vl[LSEQ * DMODEL];
__device__ __nv_bfloat16 g_ah[LSEQ * DMODEL], g_al[LSEQ * DMODEL];
__device__ __nv_bfloat16 g_wh[4 * DSQ], g_wl[4 * DSQ];   // Wq,Wk,Wv,Wo
__device__ float g_cos[LSEQ * 32];
__device__ float g_sin[LSEQ * 32];

// =================== helpers ===================
__device__ __forceinline__ uint32_t smem_u32(const void* p) {
    uint32_t a;
    asm("{ .reg .u64 t; cvta.to.shared.u64 t, %1; cvt.u32.u64 %0, t; }"
        : "=r"(a) : "l"(p));
    return a;
}

__device__ __forceinline__ void ldsm_x4(uint32_t& r0, uint32_t& r1,
                                        uint32_t& r2, uint32_t& r3,
                                        uint32_t addr) {
    asm volatile("ldmatrix.sync.aligned.m8n8.x4.shared.b16 {%0,%1,%2,%3}, [%4];"
                 : "=r"(r0), "=r"(r1), "=r"(r2), "=r"(r3) : "r"(addr));
}

__device__ __forceinline__ void ldsm_x4_t(uint32_t& r0, uint32_t& r1,
                                          uint32_t& r2, uint32_t& r3,
                                          uint32_t addr) {
    asm volatile("ldmatrix.sync.aligned.m8n8.x4.trans.shared.b16 {%0,%1,%2,%3}, [%4];"
                 : "=r"(r0), "=r"(r1), "=r"(r2), "=r"(r3) : "r"(addr));
}

__device__ __forceinline__ void mma16816(float* d, const uint32_t* a,
                                         const uint32_t* b) {
    asm volatile(
        "mma.sync.aligned.m16n8k16.row.col.f32.bf16.bf16.f32 "
        "{%0,%1,%2,%3}, {%4,%5,%6,%7}, {%8,%9}, {%0,%1,%2,%3};"
        : "+f"(d[0]), "+f"(d[1]), "+f"(d[2]), "+f"(d[3])
        : "r"(a[0]), "r"(a[1]), "r"(a[2]), "r"(a[3]), "r"(b[0]), "r"(b[1]));
}

__device__ __forceinline__ void pack_hilo(float x, float y,
                                          uint32_t& hi, uint32_t& lo) {
    __nv_bfloat162 h = __float22bfloat162_rn(make_float2(x, y));
    float2 hf = __bfloat1622float2(h);
    __nv_bfloat162 l = __float22bfloat162_rn(make_float2(x - hf.x, y - hf.y));
    hi = *reinterpret_cast<uint32_t*>(&h);
    lo = *reinterpret_cast<uint32_t*>(&l);
}

__device__ __forceinline__ void store_bf2(__nv_bfloat16* dh, __nv_bfloat16* dl,
                                          size_t idx, float x, float y) {
    uint32_t hi, lo;
    pack_hilo(x, y, hi, lo);
    *reinterpret_cast<uint32_t*>(dh + idx) = hi;
    *reinterpret_cast<uint32_t*>(dl + idx) = lo;
}

// ---------------- fp32 -> bf16 hi/lo conversion pass ----------------
__global__ __launch_bounds__(256) void cvt_kernel(
    const float* __restrict__ x, const float* __restrict__ Wq,
    const float* __restrict__ Wk, const float* __restrict__ Wv,
    const float* __restrict__ Wo) {
    const int z = blockIdx.z;
    const float* src;
    __nv_bfloat16 *dh, *dl;
    int n;
    if (z == 0) { src = x; dh = g_xh; dl = g_xl; n = LSEQ * DMODEL; }
    else {
        src = (z == 1) ? Wq : (z == 2) ? Wk : (z == 3) ? Wv : Wo;
        dh = g_wh + (z - 1) * DSQ; dl = g_wl + (z - 1) * DSQ; n = DSQ;
    }
    int idx = (blockIdx.x * 256 + threadIdx.x) * 4;
    if (idx >= n) return;
    float4 v = *reinterpret_cast<const float4*>(src + idx);
    uint32_t h0, l0, h1, l1;
    pack_hilo(v.x, v.y, h0, l0);
    pack_hilo(v.z, v.w, h1, l1);
    *reinterpret_cast<uint2*>(dh + idx) = make_uint2(h0, h1);
    *reinterpret_cast<uint2*>(dl + idx) = make_uint2(l0, l1);
}

// ======== bf16x3 HMMA GEMM (pre-split bf16 inputs) ========
#define BM 128
#define BN 128
#define BK 32
#define ROWB 80
#define OFF_AH 0
#define OFF_AL (128 * ROWB)
#define OFF_BH (2 * 128 * ROWB)
#define OFF_BL (3 * 128 * ROWB)
#define STAGE_BYTES (4 * 128 * ROWB)
#define GEMM_SMEM (2 * STAGE_BYTES)

// computes acc for tile (bm,bn); caller does epilogue
__device__ __forceinline__ void gemm_bf_body(
    const __nv_bfloat16* __restrict__ Ah, const __nv_bfloat16* __restrict__ Al,
    const __nv_bfloat16* __restrict__ Bh, const __nv_bfloat16* __restrict__ Bl,
    char* smem, int bm, int bn, float acc[2][8][4]) {
    const uint32_t sbase = smem_u32(smem);
    const int tid = threadIdx.x;
    const int wid = tid >> 5;
    const int lane = tid & 31;
    const int warp_m = wid & 3;
    const int warp_n = wid >> 2;

#pragma unroll
    for (int i = 0; i < 2; i++)
#pragma unroll
        for (int j = 0; j < 8; j++)
#pragma unroll
            for (int k = 0; k < 4; k++) acc[i][j][k] = 0.f;

    const int lrow = tid >> 1;            // 0..127
    const int h16 = (tid & 1) * 16;       // element offset within 32-elem chunk

    const int a_row = lane & 15;
    const int a_byte = (lane >> 4) << 4;
    const int b_grp = lane >> 3;
    const int b_row = (lane & 7) + ((b_grp >> 1) << 3);
    const int b_byte = (b_grp & 1) << 4;

    const __nv_bfloat16* Arh = Ah + (size_t)(bm + lrow) * DMODEL + h16;
    const __nv_bfloat16* Arl = Al + (size_t)(bm + lrow) * DMODEL + h16;
    const __nv_bfloat16* Brh = Bh + (size_t)(bn + lrow) * DMODEL + h16;
    const __nv_bfloat16* Brl = Bl + (size_t)(bn + lrow) * DMODEL + h16;
    const uint32_t soff = (uint32_t)(lrow * ROWB + h16 * 2);   // 16 elems = 32B

    // ---- prologue: chunk 0 -> stage 0 ----
#pragma unroll
    for (int j = 0; j < 2; j++) {
        *reinterpret_cast<uint4*>(smem + OFF_AH + soff + j * 16) =
            *reinterpret_cast<const uint4*>(Arh + j * 8);
        *reinterpret_cast<uint4*>(smem + OFF_AL + soff + j * 16) =
            *reinterpret_cast<const uint4*>(Arl + j * 8);
        *reinterpret_cast<uint4*>(smem + OFF_BH + soff + j * 16) =
            *reinterpret_cast<const uint4*>(Brh + j * 8);
        *reinterpret_cast<uint4*>(smem + OFF_BL + soff + j * 16) =
            *reinterpret_cast<const uint4*>(Brl + j * 8);
    }
    __syncthreads();

    uint4 pah[2], pal[2], pbh[2], pbl[2];
    for (int c = 0; c < 32; c++) {
        const int cur = c & 1;
        if (c < 31) {
            const int kb = (c + 1) * BK;
#pragma unroll
            for (int j = 0; j < 2; j++) {
                pah[j] = *reinterpret_cast<const uint4*>(Arh + kb + j * 8);
                pal[j] = *reinterpret_cast<const uint4*>(Arl + kb + j * 8);
                pbh[j] = *reinterpret_cast<const uint4*>(Brh + kb + j * 8);
                pbl[j] = *reinterpret_cast<const uint4*>(Brl + kb + j * 8);
            }
        }

        const uint32_t st = sbase + cur * STAGE_BYTES;
        const uint32_t sAh = st + OFF_AH + (warp_m * 32 + a_row) * ROWB + a_byte;
        const uint32_t sAl = st + OFF_AL + (warp_m * 32 + a_row) * ROWB + a_byte;
        const uint32_t sBh = st + OFF_BH + (warp_n * 64 + b_row) * ROWB + b_byte;
        const uint32_t sBl = st + OFF_BL + (warp_n * 64 + b_row) * ROWB + b_byte;
#pragma unroll
        for (int ks = 0; ks < 2; ks++) {
            uint32_t ah[2][4], al[2][4], bh[8][2], bl[8][2];
#pragma unroll
            for (int mt = 0; mt < 2; mt++) {
                ldsm_x4(ah[mt][0], ah[mt][1], ah[mt][2], ah[mt][3],
                        sAh + mt * 16 * ROWB + ks * 32);
                ldsm_x4(al[mt][0], al[mt][1], al[mt][2], al[mt][3],
                        sAl + mt * 16 * ROWB + ks * 32);
            }
#pragma unroll
            for (int np = 0; np < 4; np++) {
                ldsm_x4(bh[2 * np][0], bh[2 * np][1], bh[2 * np + 1][0],
                        bh[2 * np + 1][1], sBh + np * 16 * ROWB + ks * 32);
                ldsm_x4(bl[2 * np][0], bl[2 * np][1], bl[2 * np + 1][0],
                        bl[2 * np + 1][1], sBl + np * 16 * ROWB + ks * 32);
            }
#pragma unroll
            for (int mt = 0; mt < 2; mt++)
#pragma unroll
                for (int nt = 0; nt < 8; nt++) mma16816(acc[mt][nt], ah[mt], bh[nt]);
#pragma unroll
            for (int mt = 0; mt < 2; mt++)
#pragma unroll
                for (int nt = 0; nt < 8; nt++) mma16816(acc[mt][nt], ah[mt], bl[nt]);
#pragma unroll
            for (int mt = 0; mt < 2; mt++)
#pragma unroll
                for (int nt = 0; nt < 8; nt++) mma16816(acc[mt][nt], al[mt], bh[nt]);
        }
        __syncthreads();

        if (c < 31) {
            char* sn = smem + (cur ^ 1) * STAGE_BYTES;
#pragma unroll
            for (int j = 0; j < 2; j++) {
                *reinterpret_cast<uint4*>(sn + OFF_AH + soff + j * 16) = pah[j];
                *reinterpret_cast<uint4*>(sn + OFF_AL + soff + j * 16) = pal[j];
                *reinterpret_cast<uint4*>(sn + OFF_BH + soff + j * 16) = pbh[j];
                *reinterpret_cast<uint4*>(sn + OFF_BL + soff + j * 16) = pbl[j];
            }
            __syncthreads();
        }
    }
}

__global__ __launch_bounds__(256, 1) void gemm_qkv_kernel() {
    extern __shared__ char smem[];
    const int z = blockIdx.z;
    const int bm = blockIdx.x * BM;
    const int bn = blockIdx.y * BN;
    float acc[2][8][4];
    gemm_bf_body(g_xh, g_xl, g_wh + z * DSQ, g_wl + z * DSQ, smem, bm, bn, acc);

    const int wid = threadIdx.x >> 5;
    const int lane = threadIdx.x & 31;
    const int warp_m = wid & 3;
    const int warp_n = wid >> 2;
    if (z == 2) {   // V: write bf16 hi/lo directly
#pragma unroll
        for (int mt = 0; mt < 2; mt++) {
            const int r0 = bm + warp_m * 32 + mt * 16 + (lane >> 2);
#pragma unroll
            for (int nt = 0; nt < 8; nt++) {
                const int col = bn + warp_n * 64 + nt * 8 + (lane & 3) * 2;
                store_bf2(g_vh, g_vl, (size_t)r0 * DMODEL + col,
                          acc[mt][nt][0], acc[mt][nt][1]);
                store_bf2(g_vh, g_vl, (size_t)(r0 + 8) * DMODEL + col,
                          acc[mt][nt][2], acc[mt][nt][3]);
            }
        }
    } else {        // Q/K: fp32 for RoPE
        float* C = z ? g_K : g_Q;
#pragma unroll
        for (int mt = 0; mt < 2; mt++) {
            const int r0 = bm + warp_m * 32 + mt * 16 + (lane >> 2);
#pragma unroll
            for (int nt = 0; nt < 8; nt++) {
                const int col = bn + warp_n * 64 + nt * 8 + (lane & 3) * 2;
                *reinterpret_cast<float2*>(C + (size_t)r0 * DMODEL + col) =
                    make_float2(acc[mt][nt][0], acc[mt][nt][1]);
                *reinterpret_cast<float2*>(C + (size_t)(r0 + 8) * DMODEL + col) =
                    make_float2(acc[mt][nt][2], acc[mt][nt][3]);
            }
        }
    }
}

__global__ __launch_bounds__(256, 1) void gemm_out_kernel(float* __restrict__ out) {
    extern __shared__ char smem[];
    const int bm = blockIdx.x * BM;
    const int bn = blockIdx.y * BN;
    float acc[2][8][4];
    gemm_bf_body(g_ah, g_al, g_wh + 3 * DSQ, g_wl + 3 * DSQ, smem, bm, bn, acc);

    const int wid = threadIdx.x >> 5;
    const int lane = threadIdx.x & 31;
    const int warp_m = wid & 3;
    const int warp_n = wid >> 2;
#pragma unroll
    for (int mt = 0; mt < 2; mt++) {
        const int r0 = bm + warp_m * 32 + mt * 16 + (lane >> 2);
#pragma unroll
        for (int nt = 0; nt < 8; nt++) {
            const int col = bn + warp_n * 64 + nt * 8 + (lane & 3) * 2;
            *reinterpret_cast<float2*>(out + (size_t)r0 * DMODEL + col) =
                make_float2(acc[mt][nt][0], acc[mt][nt][1]);
            *reinterpret_cast<float2*>(out + (size_t)(r0 + 8) * DMODEL + col) =
                make_float2(acc[mt][nt][2], acc[mt][nt][3]);
        }
    }
}

// ---------------- RoPE tables --------------------------------
__global__ void rope_tables_kernel() {
    int l = blockIdx.x;
    int j = threadIdx.x;
    float e = (float)(2 * j) / 64.0f;
    float inv = (float)pow(10000.0, -(double)e);
    float freq = (float)l * inv;
    double s, c;
    sincos((double)freq, &s, &c);
    g_cos[l * 32 + j] = (float)c;
    g_sin[l * 32 + j] = (float)s;
}

// ---------------- RoPE apply: fp32 Q/K -> bf16 hi/lo -------
__global__ __launch_bounds__(128) void rope_apply_kernel() {
    int gw = blockIdx.x * 4 + (threadIdx.x >> 5);
    int lane = threadIdx.x & 31;
    int l = gw >> 4;
    int h = gw & 15;
    float c = g_cos[l * 32 + lane];
    float s = g_sin[l * 32 + lane];
    const size_t base = (size_t)l * DMODEL + h * DHEAD;
    const float* q = g_Q + base;
    const float* k = g_K + base;
    float q1 = q[2 * lane], q2 = q[2 * lane + 1];
    float k1 = k[2 * lane], k2 = k[2 * lane + 1];
    float qo1 = q1 * c - q2 * s, qo2 = q1 * s + q2 * c;
    float ko1 = k1 * c - k2 * s, ko2 = k1 * s + k2 * c;
    __nv_bfloat16 hq1 = __float2bfloat16(qo1);
    __nv_bfloat16 hq2 = __float2bfloat16(qo2);
    __nv_bfloat16 hk1 = __float2bfloat16(ko1);
    __nv_bfloat16 hk2 = __float2bfloat16(ko2);
    g_qh[base + lane] = hq1;
    g_ql[base + lane] = __float2bfloat16(qo1 - __bfloat162float(hq1));
    g_qh[base + lane + 32] = hq2;
    g_ql[base + lane + 32] = __float2bfloat16(qo2 - __bfloat162float(hq2));
    g_kh[base + lane] = hk1;
    g_kl[base + lane] = __float2bfloat16(ko1 - __bfloat162float(hk1));
    g_kh[base + lane + 32] = hk2;
    g_kl[base + lane + 32] = __float2bfloat16(ko2 - __bfloat162float(hk2));
}

// ======== bf16x3 HMMA causal flash attention (pipelined, pre-split) ========
#define FROWB 144
#define FBUF 36864
#define F_KL 9216
#define F_VH 18432
#define F_VL 27648
#define FLASH_SMEM (2 * FBUF)

__global__ __launch_bounds__(256) void flash_mma_kernel() {
    extern __shared__ char sm[];
    const uint32_t sbase = smem_u32(sm);
    const int tid = threadIdx.x;
    const int wid = tid >> 5;
    const int lane = tid & 31;
    const int qb = 31 - blockIdx.y;
    const int h = blockIdx.x;
    const int hoff = h * DHEAD;

    // ---- stage Q block (128 x 64) hi/lo into buffer 0 (pure copy) ----
    {
        const int row = tid >> 1;
        const int half = tid & 1;             // 32 elements each
        const size_t gq = (size_t)(qb * 128 + row) * DMODEL + hoff + half * 32;
        const uint32_t off = (uint32_t)(row * FROWB + half * 64);
#pragma unroll
        for (int j = 0; j < 4; j++) {
            *reinterpret_cast<uint4*>(sm + off + j * 16) =
                *reinterpret_cast<const uint4*>(g_qh + gq + j * 8);
            *reinterpret_cast<uint4*>(sm + 18432 + off + j * 16) =
                *reinterpret_cast<const uint4*>(g_ql + gq + j * 8);
        }
    }
    __syncthreads();

    const int frow = lane & 15;
    const int fbyte = (lane >> 4) << 4;

    uint32_t qh[4][4], ql[4][4];
    {
        const uint32_t qa = sbase + (wid * 16 + frow) * FROWB + fbyte;
#pragma unroll
        for (int ks = 0; ks < 4; ks++) {
            ldsm_x4(qh[ks][0], qh[ks][1], qh[ks][2], qh[ks][3], qa + ks * 32);
            ldsm_x4(ql[ks][0], ql[ks][1], ql[ks][2], ql[ks][3],
                    qa + 18432 + ks * 32);
        }
    }
    __syncthreads();

    // K/V loader coords: 4 thr/row, 16 elements (32B) each
    const int krow = tid >> 2;
    const int q4 = tid & 3;
    const __nv_bfloat16* Khp = g_kh + (size_t)krow * DMODEL + hoff + q4 * 16;
    const __nv_bfloat16* Klp = g_kl + (size_t)krow * DMODEL + hoff + q4 * 16;
    const __nv_bfloat16* Vhp = g_vh + (size_t)krow * DMODEL + hoff + q4 * 16;
    const __nv_bfloat16* Vlp = g_vl + (size_t)krow * DMODEL + hoff + q4 * 16;
    const uint32_t soff = (uint32_t)(krow * FROWB + q4 * 32);

    // ---- tile 0 into buffer 0 ----
#pragma unroll
    for (int j = 0; j < 2; j++) {
        *reinterpret_cast<uint4*>(sm + soff + j * 16) =
            *reinterpret_cast<const uint4*>(Khp + j * 8);
        *reinterpret_cast<uint4*>(sm + F_KL + soff + j * 16) =
            *reinterpret_cast<const uint4*>(Klp + j * 8);
        *reinterpret_cast<uint4*>(sm + F_VH + soff + j * 16) =
            *reinterpret_cast<const uint4*>(Vhp + j * 8);
        *reinterpret_cast<uint4*>(sm + F_VL + soff + j * 16) =
            *reinterpret_cast<const uint4*>(Vlp + j * 8);
    }
    __syncthreads();

    float o[8][4];
#pragma unroll
    for (int i = 0; i < 8; i++)
#pragma unroll
        for (int j = 0; j < 4; j++) o[i][j] = 0.f;
    float m_a = -1e30f, m_b = -1e30f, l_a = 0.f, l_b = 0.f;

    const int ncol = (lane & 3) * 2;
    const int qga = qb * 128 + wid * 16 + (lane >> 2);
    const int qgb = qga + 8;

    const int b_grp = lane >> 3;
    const int b_row = (lane & 7) + ((b_grp >> 1) << 3);
    const int b_byte = (b_grp & 1) << 4;

    const int nkt = (qb + 1) * 2;
    uint4 pkh[2], pkl[2], pvh[2], pvl[2];
    for (int kt = 0; kt < nkt; kt++) {
        const int kbase = kt * 64;
        const uint32_t bb = sbase + (uint32_t)(kt & 1) * FBUF;

        // ---- prefetch next tile into registers ----
        if (kt + 1 < nkt) {
            const size_t nb = (size_t)(kbase + 64) * DMODEL;
#pragma unroll
            for (int j = 0; j < 2; j++) {
                pkh[j] = *reinterpret_cast<const uint4*>(Khp + nb + j * 8);
                pkl[j] = *reinterpret_cast<const uint4*>(Klp + nb + j * 8);
                pvh[j] = *reinterpret_cast<const uint4*>(Vhp + nb + j * 8);
                pvl[j] = *reinterpret_cast<const uint4*>(Vlp + nb + j * 8);
            }
        }

        // ---- S = Q K^T (bf16x3) ----
        float s[8][4];
#pragma unroll
        for (int i = 0; i < 8; i++)
#pragma unroll
            for (int j = 0; j < 4; j++) s[i][j] = 0.f;

#pragma unroll
        for (int ks = 0; ks < 4; ks++) {
            uint32_t kf[8][2];
#pragma unroll
            for (int np = 0; np < 4; np++)
                ldsm_x4(kf[2 * np][0], kf[2 * np][1], kf[2 * np + 1][0],
                        kf[2 * np + 1][1],
                        bb + (np * 16 + b_row) * FROWB + b_byte + ks * 32);
#pragma unroll
            for (int nt = 0; nt < 8; nt++) mma16816(s[nt], qh[ks], kf[nt]);
#pragma unroll
            for (int nt = 0; nt < 8; nt++) mma16816(s[nt], ql[ks], kf[nt]);
#pragma unroll
            for (int np = 0; np < 4; np++)
                ldsm_x4(kf[2 * np][0], kf[2 * np][1], kf[2 * np + 1][0],
                        kf[2 * np + 1][1],
                        bb + F_KL + (np * 16 + b_row) * FROWB + b_byte + ks * 32);
#pragma unroll
            for (int nt = 0; nt < 8; nt++) mma16816(s[nt], qh[ks], kf[nt]);
        }

        // ---- scale + causal mask ----
        const bool needmask = (kbase + 63) > (qb * 128 + wid * 16);
#pragma unroll
        for (int nt = 0; nt < 8; nt++)
#pragma unroll
            for (int c = 0; c < 4; c++) {
                float sv = s[nt][c] * 0.125f;
                if (needmask) {
                    int kg = kbase + nt * 8 + ncol + (c & 1);
                    int qg = (c < 2) ? qga : qgb;
                    if (kg > qg) sv = -1e30f;
                }
                s[nt][c] = sv;
            }

        // ---- online softmax ----
        float ra = -1e30f, rb = -1e30f;
#pragma unroll
        for (int nt = 0; nt < 8; nt++) {
            ra = fmaxf(ra, fmaxf(s[nt][0], s[nt][1]));
            rb = fmaxf(rb, fmaxf(s[nt][2], s[nt][3]));
        }
        ra = fmaxf(ra, __shfl_xor_sync(0xffffffffu, ra, 1));
        ra = fmaxf(ra, __shfl_xor_sync(0xffffffffu, ra, 2));
        rb = fmaxf(rb, __shfl_xor_sync(0xffffffffu, rb, 1));
        rb = fmaxf(rb, __shfl_xor_sync(0xffffffffu, rb, 2));
        float mna = fmaxf(m_a, ra), mnb = fmaxf(m_b, rb);
        float aa = __expf(m_a - mna), ab = __expf(m_b - mnb);
        m_a = mna; m_b = mnb;
        float psa = 0.f, psb = 0.f;
#pragma unroll
        for (int nt = 0; nt < 8; nt++) {
            s[nt][0] = __expf(s[nt][0] - m_a);
            s[nt][1] = __expf(s[nt][1] - m_a);
            s[nt][2] = __expf(s[nt][2] - m_b);
            s[nt][3] = __expf(s[nt][3] - m_b);
            psa += s[nt][0] + s[nt][1];
            psb += s[nt][2] + s[nt][3];
        }
        psa += __shfl_xor_sync(0xffffffffu, psa, 1);
        psa += __shfl_xor_sync(0xffffffffu, psa, 2);
        psb += __shfl_xor_sync(0xffffffffu, psb, 1);
        psb += __shfl_xor_sync(0xffffffffu, psb, 2);
        l_a = l_a * aa + psa;
        l_b = l_b * ab + psb;
#pragma unroll
        for (int nt = 0; nt < 8; nt++) {
            o[nt][0] *= aa; o[nt][1] *= aa;
            o[nt][2] *= ab; o[nt][3] *= ab;
        }

        // ---- O += P V (bf16x3) ----
#pragma unroll
        for (int js = 0; js < 4; js++) {
            uint32_t pph[4], ppl[4];
            pack_hilo(s[2 * js][0], s[2 * js][1], pph[0], ppl[0]);
            pack_hilo(s[2 * js][2], s[2 * js][3], pph[1], ppl[1]);
            pack_hilo(s[2 * js + 1][0], s[2 * js + 1][1], pph[2], ppl[2]);
            pack_hilo(s[2 * js + 1][2], s[2 * js + 1][3], pph[3], ppl[3]);

            uint32_t vf[8][2];
#pragma unroll
            for (int dp = 0; dp < 4; dp++)
                ldsm_x4_t(vf[2 * dp][0], vf[2 * dp][1], vf[2 * dp + 1][0],
                          vf[2 * dp + 1][1],
                          bb + F_VH + (js * 16 + frow) * FROWB + dp * 32 + fbyte);
#pragma unroll
            for (int nt = 0; nt < 8; nt++) mma16816(o[nt], pph, vf[nt]);
#pragma unroll
            for (int nt = 0; nt < 8; nt++) mma16816(o[nt], ppl, vf[nt]);
#pragma unroll
            for (int dp = 0; dp < 4; dp++)
                ldsm_x4_t(vf[2 * dp][0], vf[2 * dp][1], vf[2 * dp + 1][0],
                          vf[2 * dp + 1][1],
                          bb + F_VL + (js * 16 + frow) * FROWB + dp * 32 + fbyte);
#pragma unroll
            for (int nt = 0; nt < 8; nt++) mma16816(o[nt], pph, vf[nt]);
        }

        // ---- store prefetched tile to alternate buffer ----
        if (kt + 1 < nkt) {
            char* nbuf = sm + ((kt + 1) & 1) * FBUF;
#pragma unroll
            for (int j = 0; j < 2; j++) {
                *reinterpret_cast<uint4*>(nbuf + soff + j * 16) = pkh[j];
                *reinterpret_cast<uint4*>(nbuf + F_KL + soff + j * 16) = pkl[j];
                *reinterpret_cast<uint4*>(nbuf + F_VH + soff + j * 16) = pvh[j];
                *reinterpret_cast<uint4*>(nbuf + F_VL + soff + j * 16) = pvl[j];
            }
        }
        __syncthreads();
    }

    // ---- normalize + store bf16 hi/lo ----
    const float rla = 1.f / l_a;
    const float rlb = 1.f / l_b;
#pragma unroll
    for (int nt = 0; nt < 8; nt++) {
        store_bf2(g_ah, g_al, (size_t)qga * DMODEL + hoff + nt * 8 + ncol,
                  o[nt][0] * rla, o[nt][1] * rla);
        store_bf2(g_ah, g_al, (size_t)qgb * DMODEL + hoff + nt * 8 + ncol,
                  o[nt][2] * rlb, o[nt][3] * rlb);
    }
}

// ---------------- launch ---------------------------------------
extern "C" void kernel_launch(void* const* d_in, const int* in_sizes, int n_in,
                              void* d_out, int out_size) {
    const float* x  = (const float*)d_in[0];
    // d_in[1] = mask (tril) — fixed causal, hardcoded
    const float* Wq = (const float*)d_in[2];
    const float* Wk = (const float*)d_in[3];
    const float* Wv = (const float*)d_in[4];
    const float* Wo = (const float*)d_in[5];
    float* out = (float*)d_out;

    cudaFuncSetAttribute(gemm_qkv_kernel,
                         cudaFuncAttributeMaxDynamicSharedMemorySize, GEMM_SMEM);
    cudaFuncSetAttribute(gemm_out_kernel,
                         cudaFuncAttributeMaxDynamicSharedMemorySize, GEMM_SMEM);
    cudaFuncSetAttribute(flash_mma_kernel,
                         cudaFuncAttributeMaxDynamicSharedMemorySize, FLASH_SMEM);

    rope_tables_kernel<<<LSEQ, 32>>>();

    dim3 cgrid(LSEQ * DMODEL / 4 / 256, 1, 5);
    cvt_kernel<<<cgrid, 256>>>(x, Wq, Wk, Wv, Wo);

    dim3 qkvgrid(LSEQ / BM, DMODEL / BN, 3);
    gemm_qkv_kernel<<<qkvgrid, 256, GEMM_SMEM>>>();

    rope_apply_kernel<<<(LSEQ * NHEAD) / 4, 128>>>();

    dim3 fgrid(NHEAD, LSEQ / 128);
    flash_mma_kernel<<<fgrid, 256, FLASH_SMEM>>>();

    dim3 ogrid(LSEQ / BM, DMODEL / BN);
    gemm_out_kernel<<<ogrid, 256, GEMM_SMEM>>>(out);
}